// round 1
// baseline (speedup 1.0000x reference)
#include <cuda_runtime.h>
#include <cstdint>

#define SEQ   2048
#define DIM   1024
#define DH    64
#define NHB   32      // H*B = 16*2
#define NB    2       // batch

// Scratch (static __device__ arrays: allocation-free per harness rules)
static __device__ float g_Q[NHB * SEQ * DH];                 // [hb, s, dh], pre-scaled by 0.125
static __device__ float g_K[NHB * SEQ * DH];
static __device__ float g_V[NHB * SEQ * DH];
static __device__ float g_P[(size_t)NHB * SEQ * SEQ];        // attention scores / probs

// ---------------------------------------------------------------------------
// Kernel 1: QKV projection. Y = X[4096,1024] @ W[1024,1024], z selects W_q/k/v.
// 128x128x16 tile, 256 threads, 8x8 per thread, reg-prefetch double buffer.
// Stores split-head layout [hb, s, dh]; Q gets *0.125.
// ---------------------------------------------------------------------------
__global__ void __launch_bounds__(256) k_qkv(
    const float* __restrict__ X,
    const float* __restrict__ Wq,
    const float* __restrict__ Wk,
    const float* __restrict__ Wv)
{
    __shared__ float As[16 * 128];   // As[k][m]
    __shared__ float Bs[16 * 128];   // Bs[k][n]

    const int tid = threadIdx.x;
    const int z   = blockIdx.z;
    const float* __restrict__ W  = (z == 0) ? Wq : (z == 1) ? Wk : Wv;
    float*       __restrict__ dst = (z == 0) ? g_Q : (z == 1) ? g_K : g_V;
    const float scale = (z == 0) ? 0.125f : 1.0f;

    const int bm = blockIdx.y * 128;   // row block in [0,4096)
    const int bn = blockIdx.x * 128;   // col block in [0,1024)

    // A loader: 128 rows x 16 k, two threads per row
    const int ar = tid >> 1;
    const int ak = (tid & 1) * 8;
    // B loader: 16 rows x 128 cols
    const int br = tid >> 5;           // 0..7, plus +8
    const int bc = (tid & 31) * 4;

    const int ty = tid >> 4;           // 0..15
    const int tx = tid & 15;           // 0..15

    float acc[8][8];
#pragma unroll
    for (int i = 0; i < 8; i++)
#pragma unroll
        for (int j = 0; j < 8; j++) acc[i][j] = 0.f;

    const float* aBase = X + (size_t)(bm + ar) * DIM + ak;
    const float* bBase = W + (size_t)br * DIM + bn + bc;

    float4 pa0 = *(const float4*)(aBase);
    float4 pa1 = *(const float4*)(aBase + 4);
    float4 pb0 = *(const float4*)(bBase);
    float4 pb1 = *(const float4*)(bBase + 8 * DIM);

    const int NT = DIM / 16;
    for (int kt = 0; kt < NT; kt++) {
        // stage current tile
        As[(ak + 0) * 128 + ar] = pa0.x;
        As[(ak + 1) * 128 + ar] = pa0.y;
        As[(ak + 2) * 128 + ar] = pa0.z;
        As[(ak + 3) * 128 + ar] = pa0.w;
        As[(ak + 4) * 128 + ar] = pa1.x;
        As[(ak + 5) * 128 + ar] = pa1.y;
        As[(ak + 6) * 128 + ar] = pa1.z;
        As[(ak + 7) * 128 + ar] = pa1.w;
        *(float4*)&Bs[br * 128 + bc]       = pb0;
        *(float4*)&Bs[(br + 8) * 128 + bc] = pb1;
        __syncthreads();

        if (kt + 1 < NT) {
            const float* ap = aBase + (kt + 1) * 16;
            pa0 = *(const float4*)(ap);
            pa1 = *(const float4*)(ap + 4);
            const float* bp = bBase + (size_t)(kt + 1) * 16 * DIM;
            pb0 = *(const float4*)(bp);
            pb1 = *(const float4*)(bp + 8 * DIM);
        }

#pragma unroll
        for (int k = 0; k < 16; k++) {
            float a[8], b[8];
            *(float4*)&a[0] = *(const float4*)&As[k * 128 + ty * 8];
            *(float4*)&a[4] = *(const float4*)&As[k * 128 + ty * 8 + 4];
            *(float4*)&b[0] = *(const float4*)&Bs[k * 128 + tx * 8];
            *(float4*)&b[4] = *(const float4*)&Bs[k * 128 + tx * 8 + 4];
#pragma unroll
            for (int i = 0; i < 8; i++)
#pragma unroll
                for (int j = 0; j < 8; j++) acc[i][j] += a[i] * b[j];
        }
        __syncthreads();
    }

    // Epilogue: split heads. col j = h*64 + d; 8-wide chunks never straddle heads.
    const int colBase = bn + tx * 8;
    const int h  = colBase >> 6;
    const int d0 = colBase & 63;
#pragma unroll
    for (int i = 0; i < 8; i++) {
        const int m  = bm + ty * 8 + i;
        const int bb = m >> 11;                // batch
        const int s  = m & (SEQ - 1);
        float* o = dst + ((size_t)(h * NB + bb) * SEQ + s) * DH + d0;
        float4 v0 = make_float4(acc[i][0] * scale, acc[i][1] * scale,
                                acc[i][2] * scale, acc[i][3] * scale);
        float4 v1 = make_float4(acc[i][4] * scale, acc[i][5] * scale,
                                acc[i][6] * scale, acc[i][7] * scale);
        *(float4*)(o)     = v0;
        *(float4*)(o + 4) = v1;
    }
}

// ---------------------------------------------------------------------------
// Kernel 2: scores = Q @ K^T per (h,b). NT GEMM, M=N=2048, K=64.
// Both operands row-major [S,64] => identical transposing loaders.
// ---------------------------------------------------------------------------
__global__ void __launch_bounds__(256) k_scores()
{
    __shared__ float As[16 * 128];   // As[k][m]  (from Q rows)
    __shared__ float Bs[16 * 128];   // Bs[k][n]  (from K rows)

    const int tid = threadIdx.x;
    const int z   = blockIdx.z;
    const float* __restrict__ Q = g_Q + (size_t)z * SEQ * DH;
    const float* __restrict__ K = g_K + (size_t)z * SEQ * DH;

    const int bm = blockIdx.y * 128;   // query rows
    const int bn = blockIdx.x * 128;   // key rows

    const int ar = tid >> 1;
    const int ak = (tid & 1) * 8;
    const int ty = tid >> 4;
    const int tx = tid & 15;

    float acc[8][8];
#pragma unroll
    for (int i = 0; i < 8; i++)
#pragma unroll
        for (int j = 0; j < 8; j++) acc[i][j] = 0.f;

    const float* aBase = Q + (size_t)(bm + ar) * DH + ak;
    const float* bBase = K + (size_t)(bn + ar) * DH + ak;

    float4 pa0 = *(const float4*)(aBase);
    float4 pa1 = *(const float4*)(aBase + 4);
    float4 pb0 = *(const float4*)(bBase);
    float4 pb1 = *(const float4*)(bBase + 4);

    const int NT = DH / 16;   // 4
    for (int kt = 0; kt < NT; kt++) {
        As[(ak + 0) * 128 + ar] = pa0.x;
        As[(ak + 1) * 128 + ar] = pa0.y;
        As[(ak + 2) * 128 + ar] = pa0.z;
        As[(ak + 3) * 128 + ar] = pa0.w;
        As[(ak + 4) * 128 + ar] = pa1.x;
        As[(ak + 5) * 128 + ar] = pa1.y;
        As[(ak + 6) * 128 + ar] = pa1.z;
        As[(ak + 7) * 128 + ar] = pa1.w;
        Bs[(ak + 0) * 128 + ar] = pb0.x;
        Bs[(ak + 1) * 128 + ar] = pb0.y;
        Bs[(ak + 2) * 128 + ar] = pb0.z;
        Bs[(ak + 3) * 128 + ar] = pb0.w;
        Bs[(ak + 4) * 128 + ar] = pb1.x;
        Bs[(ak + 5) * 128 + ar] = pb1.y;
        Bs[(ak + 6) * 128 + ar] = pb1.z;
        Bs[(ak + 7) * 128 + ar] = pb1.w;
        __syncthreads();

        if (kt + 1 < NT) {
            const float* ap = aBase + (kt + 1) * 16;
            pa0 = *(const float4*)(ap);
            pa1 = *(const float4*)(ap + 4);
            const float* bp = bBase + (kt + 1) * 16;
            pb0 = *(const float4*)(bp);
            pb1 = *(const float4*)(bp + 4);
        }

#pragma unroll
        for (int k = 0; k < 16; k++) {
            float a[8], b[8];
            *(float4*)&a[0] = *(const float4*)&As[k * 128 + ty * 8];
            *(float4*)&a[4] = *(const float4*)&As[k * 128 + ty * 8 + 4];
            *(float4*)&b[0] = *(const float4*)&Bs[k * 128 + tx * 8];
            *(float4*)&b[4] = *(const float4*)&Bs[k * 128 + tx * 8 + 4];
#pragma unroll
            for (int i = 0; i < 8; i++)
#pragma unroll
                for (int j = 0; j < 8; j++) acc[i][j] += a[i] * b[j];
        }
        __syncthreads();
    }

    float* Pz = g_P + (size_t)z * SEQ * SEQ;
#pragma unroll
    for (int i = 0; i < 8; i++) {
        float* o = Pz + (size_t)(bm + ty * 8 + i) * SEQ + bn + tx * 8;
        *(float4*)(o)     = *(float4*)&acc[i][0];
        *(float4*)(o + 4) = *(float4*)&acc[i][4];
    }
}

// ---------------------------------------------------------------------------
// Kernel 3: row softmax over P. One block (256 thr) per row of 2048.
// ---------------------------------------------------------------------------
__global__ void __launch_bounds__(256) k_softmax()
{
    const int tid = threadIdx.x;
    float* row = g_P + ((size_t)blockIdx.y * SEQ + blockIdx.x) * SEQ;
    float4* r4 = (float4*)row;

    float4 v0 = r4[tid];
    float4 v1 = r4[tid + 256];

    __shared__ float red[8];
    __shared__ float bval;

    float m = fmaxf(fmaxf(fmaxf(v0.x, v0.y), fmaxf(v0.z, v0.w)),
                    fmaxf(fmaxf(v1.x, v1.y), fmaxf(v1.z, v1.w)));
#pragma unroll
    for (int o = 16; o > 0; o >>= 1) m = fmaxf(m, __shfl_xor_sync(0xffffffffu, m, o));
    if ((tid & 31) == 0) red[tid >> 5] = m;
    __syncthreads();
    if (tid == 0) {
        float t = red[0];
#pragma unroll
        for (int i = 1; i < 8; i++) t = fmaxf(t, red[i]);
        bval = t;
    }
    __syncthreads();
    m = bval;

    v0.x = __expf(v0.x - m); v0.y = __expf(v0.y - m);
    v0.z = __expf(v0.z - m); v0.w = __expf(v0.w - m);
    v1.x = __expf(v1.x - m); v1.y = __expf(v1.y - m);
    v1.z = __expf(v1.z - m); v1.w = __expf(v1.w - m);

    float s = (v0.x + v0.y + v0.z + v0.w) + (v1.x + v1.y + v1.z + v1.w);
#pragma unroll
    for (int o = 16; o > 0; o >>= 1) s += __shfl_xor_sync(0xffffffffu, s, o);
    if ((tid & 31) == 0) red[tid >> 5] = s;
    __syncthreads();
    if (tid == 0) {
        float t = 0.f;
#pragma unroll
        for (int i = 0; i < 8; i++) t += red[i];
        bval = 1.f / t;
    }
    __syncthreads();
    const float inv = bval;

    v0.x *= inv; v0.y *= inv; v0.z *= inv; v0.w *= inv;
    v1.x *= inv; v1.y *= inv; v1.z *= inv; v1.w *= inv;
    r4[tid]       = v0;
    r4[tid + 256] = v1;
}

// ---------------------------------------------------------------------------
// Kernel 4: O = P @ V per (h,b). M=2048, N=64, K=2048.
// 256x64x16 tile, 256 threads, 8x8 per thread. Writes final output layout.
// ---------------------------------------------------------------------------
__global__ void __launch_bounds__(256) k_pv(float* __restrict__ out)
{
    __shared__ float As[16 * 256];   // As[k][m]
    __shared__ float Bs[16 * 64];    // Bs[k][d]

    const int tid = threadIdx.x;
    const int z   = blockIdx.z;
    const float* __restrict__ P = g_P + (size_t)z * SEQ * SEQ;
    const float* __restrict__ V = g_V + (size_t)z * SEQ * DH;

    const int bm = blockIdx.y * 256;

    const int br = tid >> 4;          // 0..15
    const int bc = (tid & 15) * 4;    // 0..60
    const int ty = tid >> 3;          // 0..31 -> rows ty*8..+8
    const int tx = (tid & 7) * 8;     // 0..56 -> cols tx..+8

    float acc[8][8];
#pragma unroll
    for (int i = 0; i < 8; i++)
#pragma unroll
        for (int j = 0; j < 8; j++) acc[i][j] = 0.f;

    const float* aBase = P + (size_t)(bm + tid) * SEQ;
    const float* bBase = V + (size_t)br * DH + bc;

    float4 pa0 = *(const float4*)(aBase);
    float4 pa1 = *(const float4*)(aBase + 4);
    float4 pa2 = *(const float4*)(aBase + 8);
    float4 pa3 = *(const float4*)(aBase + 12);
    float4 pb  = *(const float4*)(bBase);

    const int NT = SEQ / 16;   // 128
    for (int kt = 0; kt < NT; kt++) {
        As[ 0 * 256 + tid] = pa0.x;
        As[ 1 * 256 + tid] = pa0.y;
        As[ 2 * 256 + tid] = pa0.z;
        As[ 3 * 256 + tid] = pa0.w;
        As[ 4 * 256 + tid] = pa1.x;
        As[ 5 * 256 + tid] = pa1.y;
        As[ 6 * 256 + tid] = pa1.z;
        As[ 7 * 256 + tid] = pa1.w;
        As[ 8 * 256 + tid] = pa2.x;
        As[ 9 * 256 + tid] = pa2.y;
        As[10 * 256 + tid] = pa2.z;
        As[11 * 256 + tid] = pa2.w;
        As[12 * 256 + tid] = pa3.x;
        As[13 * 256 + tid] = pa3.y;
        As[14 * 256 + tid] = pa3.z;
        As[15 * 256 + tid] = pa3.w;
        *(float4*)&Bs[br * 64 + bc] = pb;
        __syncthreads();

        if (kt + 1 < NT) {
            const float* ap = aBase + (kt + 1) * 16;
            pa0 = *(const float4*)(ap);
            pa1 = *(const float4*)(ap + 4);
            pa2 = *(const float4*)(ap + 8);
            pa3 = *(const float4*)(ap + 12);
            pb  = *(const float4*)(bBase + (size_t)(kt + 1) * 16 * DH);
        }

#pragma unroll
        for (int k = 0; k < 16; k++) {
            float a[8], b[8];
            *(float4*)&a[0] = *(const float4*)&As[k * 256 + ty * 8];
            *(float4*)&a[4] = *(const float4*)&As[k * 256 + ty * 8 + 4];
            *(float4*)&b[0] = *(const float4*)&Bs[k * 64 + tx];
            *(float4*)&b[4] = *(const float4*)&Bs[k * 64 + tx + 4];
#pragma unroll
            for (int i = 0; i < 8; i++)
#pragma unroll
                for (int j = 0; j < 8; j++) acc[i][j] += a[i] * b[j];
        }
        __syncthreads();
    }

#pragma unroll
    for (int i = 0; i < 8; i++) {
        const int m = bm + ty * 8 + i;
        float* o = out + ((size_t)z * SEQ + m) * DH + tx;
        *(float4*)(o)     = *(float4*)&acc[i][0];
        *(float4*)(o + 4) = *(float4*)&acc[i][4];
    }
}

// ---------------------------------------------------------------------------
extern "C" void kernel_launch(void* const* d_in, const int* in_sizes, int n_in,
                              void* d_out, int out_size)
{
    const float* X  = (const float*)d_in[0];
    const float* Wq = (const float*)d_in[1];
    const float* Wk = (const float*)d_in[2];
    const float* Wv = (const float*)d_in[3];
    float* out = (float*)d_out;

    k_qkv   <<<dim3(DIM / 128, (NB * SEQ) / 128, 3), 256>>>(X, Wq, Wk, Wv);
    k_scores<<<dim3(SEQ / 128, SEQ / 128, NHB), 256>>>();
    k_softmax<<<dim3(SEQ, NHB), 256>>>();
    k_pv    <<<dim3(1, SEQ / 256, NHB), 256>>>(out);
}

// round 3
// speedup vs baseline: 2.3833x; 2.3833x over previous
#include <cuda_runtime.h>
#include <cuda_fp16.h>
#include <cstdint>

#define SEQ 2048
#define DIM 1024
#define DH  64
#define HB  32
#define NB  2
#define THR 256

// ---------------- scratch (static __device__, allocation-free) --------------
static __device__ __half g_Xh[4096*1024], g_Xl[4096*1024];
static __device__ __half g_Wth[3*1024*1024], g_Wtl[3*1024*1024];   // [z][n][k]
static __device__ __half g_Qh[HB*SEQ*DH], g_Ql[HB*SEQ*DH];         // [hb][s][dh]
static __device__ __half g_Kh[HB*SEQ*DH], g_Kl[HB*SEQ*DH];
static __device__ __half g_Vh[HB*SEQ*DH], g_Vl[HB*SEQ*DH];
static __device__ float  g_S[(size_t)HB*SEQ*SEQ];
static __device__ __half g_Ph[(size_t)HB*SEQ*SEQ], g_Pl[(size_t)HB*SEQ*SEQ];

// ---------------- helpers ---------------------------------------------------
__device__ __forceinline__ uint32_t s2u(const void* p){
    uint32_t a;
    asm("{ .reg .u64 t; cvta.to.shared.u64 t, %1; cvt.u32.u64 %0, t; }" : "=r"(a) : "l"(p));
    return a;
}
#define CPA(s,g) asm volatile("cp.async.cg.shared.global [%0], [%1], 16;" :: "r"(s), "l"(g))
#define CPA_COMMIT() asm volatile("cp.async.commit_group;" ::: "memory")
#define CPA_WAIT(n)  asm volatile("cp.async.wait_group %0;" :: "n"(n) : "memory")

__device__ __forceinline__ void ldsm4(uint32_t* r, uint32_t a){
    asm volatile("ldmatrix.sync.aligned.m8n8.x4.shared.b16 {%0,%1,%2,%3}, [%4];"
        : "=r"(r[0]), "=r"(r[1]), "=r"(r[2]), "=r"(r[3]) : "r"(a));
}
__device__ __forceinline__ void ldsm4t(uint32_t* r, uint32_t a){
    asm volatile("ldmatrix.sync.aligned.m8n8.x4.trans.shared.b16 {%0,%1,%2,%3}, [%4];"
        : "=r"(r[0]), "=r"(r[1]), "=r"(r[2]), "=r"(r[3]) : "r"(a));
}
__device__ __forceinline__ void mma16816(float* c, const uint32_t* a, uint32_t b0, uint32_t b1){
    asm volatile("mma.sync.aligned.m16n8k16.row.col.f32.f16.f16.f32 "
        "{%0,%1,%2,%3}, {%4,%5,%6,%7}, {%8,%9}, {%0,%1,%2,%3};"
        : "+f"(c[0]), "+f"(c[1]), "+f"(c[2]), "+f"(c[3])
        : "r"(a[0]), "r"(a[1]), "r"(a[2]), "r"(a[3]), "r"(b0), "r"(b1));
}
// SW128 swizzled address inside a tile of 128-byte rows
__device__ __forceinline__ uint32_t swa(uint32_t base, int r, int cb){
    uint32_t off = (uint32_t)r * 128u + (uint32_t)cb;
    return base + (off ^ ((off >> 3) & 0x70));
}
__device__ __forceinline__ void split2(float x, float y, uint32_t& hi, uint32_t& lo){
    __half hx = __float2half_rn(x), hy = __float2half_rn(y);
    __half lx = __float2half_rn(x - __half2float(hx));
    __half ly = __float2half_rn(y - __half2float(hy));
    __half2 H = __halves2half2(hx, hy), L = __halves2half2(lx, ly);
    hi = *(uint32_t*)&H; lo = *(uint32_t*)&L;
}
__device__ __forceinline__ void fsplit(float x, __half& h, __half& l){
    h = __float2half_rn(x);
    l = __float2half_rn(x - __half2float(h));
}

// cp.async a tile of `rows` x 64 fp16 (128B rows) into SW128-swizzled smem
__device__ __forceinline__ void load_tile(uint32_t sdst, const __half* g,
                                          int rows, int gstride){
    for (int i = threadIdx.x; i < rows * 8; i += THR){
        int r = i >> 3, c = i & 7;
        uint32_t off = (uint32_t)r * 128u + (uint32_t)c * 16u;
        uint32_t sw  = off ^ ((off >> 3) & 0x70);
        CPA(sdst + sw, (const char*)(g + (size_t)r * gstride) + c * 16);
    }
}

// One 64-deep K-tile of split-fp16 NT GEMM for one warp.
// WM m16-tiles per warp (m offset m0), 8 n8-tiles (n offset n0).
// BT=false: B tile stored [N][K] (128B rows). BT=true: B tile stored [K][N].
template<int WM, bool BT>
__device__ __forceinline__ void compute_ktile(
    float (*c)[8][4], uint32_t sAh, uint32_t sAl, uint32_t sBh, uint32_t sBl,
    int m0, int n0, int lane)
{
#pragma unroll
    for (int kk = 0; kk < 4; kk++){
        uint32_t aH[WM][4], aL[WM][4];
#pragma unroll
        for (int mt = 0; mt < WM; mt++){
            int rr = m0 + mt * 16 + (lane & 15);
            int cb = kk * 32 + (lane >> 4) * 16;
            ldsm4(aH[mt], swa(sAh, rr, cb));
            ldsm4(aL[mt], swa(sAl, rr, cb));
        }
        uint32_t bH[4][4], bL[4][4];
#pragma unroll
        for (int nq = 0; nq < 4; nq++){
            if (!BT){
                int rr = n0 + nq * 16 + (lane & 15);
                int cb = kk * 32 + (lane >> 4) * 16;
                ldsm4(bH[nq], swa(sBh, rr, cb));
                ldsm4(bL[nq], swa(sBl, rr, cb));
            } else {
                int rr = kk * 16 + ((lane >> 4) & 1) * 8 + (lane & 7);
                int cb = (n0 + nq * 16 + ((lane >> 3) & 1) * 8) * 2;
                ldsm4t(bH[nq], swa(sBh, rr, cb));
                ldsm4t(bL[nq], swa(sBl, rr, cb));
            }
        }
#pragma unroll
        for (int mt = 0; mt < WM; mt++)
#pragma unroll
            for (int nq = 0; nq < 4; nq++){
                // n-tile 2*nq   : b0 = r0, b1 = r2
                // n-tile 2*nq+1 : b0 = r1, b1 = r3
                mma16816(c[mt][2*nq],   aH[mt], bH[nq][0], bH[nq][2]);
                mma16816(c[mt][2*nq],   aH[mt], bL[nq][0], bL[nq][2]);
                mma16816(c[mt][2*nq],   aL[mt], bH[nq][0], bH[nq][2]);
                mma16816(c[mt][2*nq+1], aH[mt], bH[nq][1], bH[nq][3]);
                mma16816(c[mt][2*nq+1], aH[mt], bL[nq][1], bL[nq][3]);
                mma16816(c[mt][2*nq+1], aL[mt], bH[nq][1], bH[nq][3]);
            }
    }
}

// ---------------- prep: split X, split+transpose W --------------------------
__global__ void __launch_bounds__(256) k_splitX(const float4* __restrict__ X){
    int i = blockIdx.x * 256 + threadIdx.x;
    float4 v = X[i];
    uint32_t h0, l0, h1, l1;
    split2(v.x, v.y, h0, l0);
    split2(v.z, v.w, h1, l1);
    ((uint2*)g_Xh)[i] = make_uint2(h0, h1);
    ((uint2*)g_Xl)[i] = make_uint2(l0, l1);
}

__global__ void __launch_bounds__(256) k_splitW(const float* __restrict__ Wq,
                                                const float* __restrict__ Wk,
                                                const float* __restrict__ Wv){
    const int z = blockIdx.z;
    const float* __restrict__ W = (z == 0) ? Wq : (z == 1) ? Wk : Wv;
    __shared__ float t[32][33];
    int tx = threadIdx.x, ty = threadIdx.y;      // (32,8)
    int bx = blockIdx.x * 32, by = blockIdx.y * 32;
#pragma unroll
    for (int i = 0; i < 32; i += 8)
        t[ty + i][tx] = W[(size_t)(by + ty + i) * DIM + bx + tx];
    __syncthreads();
#pragma unroll
    for (int i = 0; i < 32; i += 8){
        int n = bx + ty + i, k = by + tx;
        __half h, l; fsplit(t[tx][ty + i], h, l);
        size_t o = (size_t)z * DIM * DIM + (size_t)n * DIM + k;
        g_Wth[o] = h; g_Wtl[o] = l;
    }
}

// ---------------- QKV: X[4096,1024] @ Wt[N,K]^T -----------------------------
#define QKV_STAGE 65536
#define QKV_SMEM  (2 * QKV_STAGE)
__global__ void __launch_bounds__(THR) k_qkv_mma(){
    extern __shared__ __align__(1024) char smraw[];
    uint32_t sbase = s2u(smraw);
    const int tid = threadIdx.x, w = tid >> 5, lane = tid & 31;
    const int z  = blockIdx.z;
    const int bm = blockIdx.y * 128;
    const int bn = blockIdx.x * 128;

    const __half* Ah = g_Xh + (size_t)bm * DIM;
    const __half* Al = g_Xl + (size_t)bm * DIM;
    const __half* Bh = g_Wth + (size_t)z * DIM * DIM + (size_t)bn * DIM;
    const __half* Bl = g_Wtl + (size_t)z * DIM * DIM + (size_t)bn * DIM;

    float c[2][8][4];
#pragma unroll
    for (int a = 0; a < 2; a++)
#pragma unroll
        for (int b = 0; b < 8; b++)
#pragma unroll
            for (int d = 0; d < 4; d++) c[a][b][d] = 0.f;

    const int m0 = (w >> 1) * 32, n0 = (w & 1) * 64;
    const int NT = DIM / 64;   // 16

    // prologue
    {
        uint32_t buf = sbase;
        load_tile(buf,         Ah, 128, DIM);
        load_tile(buf + 16384, Al, 128, DIM);
        load_tile(buf + 32768, Bh, 128, DIM);
        load_tile(buf + 49152, Bl, 128, DIM);
        CPA_COMMIT();
    }
    for (int kt = 0; kt < NT; kt++){
        if (kt + 1 < NT){
            uint32_t buf = sbase + ((kt + 1) & 1) * QKV_STAGE;
            load_tile(buf,         Ah + (kt+1) * 64, 128, DIM);
            load_tile(buf + 16384, Al + (kt+1) * 64, 128, DIM);
            load_tile(buf + 32768, Bh + (kt+1) * 64, 128, DIM);
            load_tile(buf + 49152, Bl + (kt+1) * 64, 128, DIM);
            CPA_COMMIT();
            CPA_WAIT(1);
        } else {
            CPA_WAIT(0);
        }
        __syncthreads();
        uint32_t buf = sbase + (kt & 1) * QKV_STAGE;
        compute_ktile<2, false>(c, buf, buf + 16384, buf + 32768, buf + 49152,
                                m0, n0, lane);
        __syncthreads();
    }

    // epilogue: split-head store, fp16 hi/lo
    const float sc = (z == 0) ? 0.125f : 1.0f;
    __half* Gh = (z == 0) ? g_Qh : (z == 1) ? g_Kh : g_Vh;
    __half* Gl = (z == 0) ? g_Ql : (z == 1) ? g_Kl : g_Vl;
#pragma unroll
    for (int mt = 0; mt < 2; mt++){
#pragma unroll
        for (int nt = 0; nt < 8; nt++){
            int n = bn + n0 + nt * 8 + (lane & 3) * 2;
            int h = n >> 6, d = n & 63;
#pragma unroll
            for (int half = 0; half < 2; half++){
                int m = bm + m0 + mt * 16 + (lane >> 2) + half * 8;
                int bb = m >> 11, s = m & (SEQ - 1);
                size_t o = ((size_t)(h * NB + bb) * SEQ + s) * DH + d;
                uint32_t hi, lo;
                split2(c[mt][nt][half*2] * sc, c[mt][nt][half*2+1] * sc, hi, lo);
                *(uint32_t*)(Gh + o) = hi;
                *(uint32_t*)(Gl + o) = lo;
            }
        }
    }
}

// ---------------- scores = Q @ K^T ------------------------------------------
#define SC_SMEM (32768 + 2 * 32768)
__global__ void __launch_bounds__(THR) k_scores_mma(){
    extern __shared__ __align__(1024) char smraw[];
    uint32_t sbase = s2u(smraw);
    const int tid = threadIdx.x, w = tid >> 5, lane = tid & 31;
    const int z  = blockIdx.z;
    const int bm = blockIdx.y * 128;
    const int bnBase = blockIdx.x * 512;

    const __half* Qh = g_Qh + ((size_t)z * SEQ + bm) * DH;
    const __half* Ql = g_Ql + ((size_t)z * SEQ + bm) * DH;

    const int m0 = (w >> 1) * 32, n0 = (w & 1) * 64;

    // prologue: A tiles + B(it=0)
    load_tile(sbase,         Qh, 128, DH);
    load_tile(sbase + 16384, Ql, 128, DH);
    {
        uint32_t buf = sbase + 32768;
        load_tile(buf,         g_Kh + ((size_t)z * SEQ + bnBase) * DH, 128, DH);
        load_tile(buf + 16384, g_Kl + ((size_t)z * SEQ + bnBase) * DH, 128, DH);
    }
    CPA_COMMIT();

    for (int it = 0; it < 4; it++){
        if (it + 1 < 4){
            uint32_t buf = sbase + 32768 + ((it + 1) & 1) * 32768;
            int bn = bnBase + (it + 1) * 128;
            load_tile(buf,         g_Kh + ((size_t)z * SEQ + bn) * DH, 128, DH);
            load_tile(buf + 16384, g_Kl + ((size_t)z * SEQ + bn) * DH, 128, DH);
            CPA_COMMIT();
            CPA_WAIT(1);
        } else {
            CPA_WAIT(0);
        }
        __syncthreads();

        float c[2][8][4];
#pragma unroll
        for (int a = 0; a < 2; a++)
#pragma unroll
            for (int b = 0; b < 8; b++)
#pragma unroll
                for (int d = 0; d < 4; d++) c[a][b][d] = 0.f;

        uint32_t buf = sbase + 32768 + (it & 1) * 32768;
        compute_ktile<2, false>(c, sbase, sbase + 16384, buf, buf + 16384,
                                m0, n0, lane);

        int bn = bnBase + it * 128;
#pragma unroll
        for (int mt = 0; mt < 2; mt++)
#pragma unroll
            for (int nt = 0; nt < 8; nt++){
                int n = bn + n0 + nt * 8 + (lane & 3) * 2;
#pragma unroll
                for (int half = 0; half < 2; half++){
                    int m = bm + m0 + mt * 16 + (lane >> 2) + half * 8;
                    float* dst = g_S + ((size_t)z * SEQ + m) * SEQ + n;
                    *(float2*)dst = make_float2(c[mt][nt][half*2], c[mt][nt][half*2+1]);
                }
            }
        __syncthreads();
    }
}

// ---------------- softmax + fp16 split --------------------------------------
__global__ void __launch_bounds__(256) k_softmax_split(){
    const int tid = threadIdx.x;
    const size_t ro = ((size_t)blockIdx.y * SEQ + blockIdx.x) * SEQ;
    const float4* r4 = (const float4*)(g_S + ro);

    float4 v0 = r4[tid];
    float4 v1 = r4[tid + 256];

    __shared__ float red[8];
    __shared__ float bval;

    float m = fmaxf(fmaxf(fmaxf(v0.x, v0.y), fmaxf(v0.z, v0.w)),
                    fmaxf(fmaxf(v1.x, v1.y), fmaxf(v1.z, v1.w)));
#pragma unroll
    for (int o = 16; o > 0; o >>= 1) m = fmaxf(m, __shfl_xor_sync(0xffffffffu, m, o));
    if ((tid & 31) == 0) red[tid >> 5] = m;
    __syncthreads();
    if (tid == 0){
        float t = red[0];
#pragma unroll
        for (int i = 1; i < 8; i++) t = fmaxf(t, red[i]);
        bval = t;
    }
    __syncthreads();
    m = bval;

    v0.x = __expf(v0.x - m); v0.y = __expf(v0.y - m);
    v0.z = __expf(v0.z - m); v0.w = __expf(v0.w - m);
    v1.x = __expf(v1.x - m); v1.y = __expf(v1.y - m);
    v1.z = __expf(v1.z - m); v1.w = __expf(v1.w - m);

    float sum = (v0.x + v0.y + v0.z + v0.w) + (v1.x + v1.y + v1.z + v1.w);
#pragma unroll
    for (int o = 16; o > 0; o >>= 1) sum += __shfl_xor_sync(0xffffffffu, sum, o);
    if ((tid & 31) == 0) red[tid >> 5] = sum;
    __syncthreads();
    if (tid == 0){
        float t = 0.f;
#pragma unroll
        for (int i = 0; i < 8; i++) t += red[i];
        bval = 1.f / t;
    }
    __syncthreads();
    const float inv = bval;

    uint32_t h0, l0, h1, l1, h2, l2, h3, l3;
    split2(v0.x * inv, v0.y * inv, h0, l0);
    split2(v0.z * inv, v0.w * inv, h1, l1);
    split2(v1.x * inv, v1.y * inv, h2, l2);
    split2(v1.z * inv, v1.w * inv, h3, l3);

    ((uint2*)(g_Ph + ro))[tid]       = make_uint2(h0, h1);
    ((uint2*)(g_Pl + ro))[tid]       = make_uint2(l0, l1);
    ((uint2*)(g_Ph + ro))[tid + 256] = make_uint2(h2, h3);
    ((uint2*)(g_Pl + ro))[tid + 256] = make_uint2(l2, l3);
}

// ---------------- O = P @ V -------------------------------------------------
#define PV_STAGE 49152
#define PV_SMEM  (2 * PV_STAGE)
__global__ void __launch_bounds__(THR) k_pv_mma(float* __restrict__ out){
    extern __shared__ __align__(1024) char smraw[];
    uint32_t sbase = s2u(smraw);
    const int tid = threadIdx.x, w = tid >> 5, lane = tid & 31;
    const int z  = blockIdx.y;
    const int bm = blockIdx.x * 128;

    const __half* Ah = g_Ph + ((size_t)z * SEQ + bm) * SEQ;
    const __half* Al = g_Pl + ((size_t)z * SEQ + bm) * SEQ;
    const __half* Bh = g_Vh + (size_t)z * SEQ * DH;   // [s][dh]
    const __half* Bl = g_Vl + (size_t)z * SEQ * DH;

    float c[1][8][4];
#pragma unroll
    for (int b = 0; b < 8; b++)
#pragma unroll
        for (int d = 0; d < 4; d++) c[0][b][d] = 0.f;

    const int m0 = w * 16, n0 = 0;
    const int NT = SEQ / 64;   // 32

    {
        uint32_t buf = sbase;
        load_tile(buf,         Ah, 128, SEQ);
        load_tile(buf + 16384, Al, 128, SEQ);
        load_tile(buf + 32768, Bh,  64, DH);
        load_tile(buf + 40960, Bl,  64, DH);
        CPA_COMMIT();
    }
    for (int kt = 0; kt < NT; kt++){
        if (kt + 1 < NT){
            uint32_t buf = sbase + ((kt + 1) & 1) * PV_STAGE;
            load_tile(buf,         Ah + (kt+1) * 64, 128, SEQ);
            load_tile(buf + 16384, Al + (kt+1) * 64, 128, SEQ);
            load_tile(buf + 32768, Bh + (size_t)(kt+1) * 64 * DH, 64, DH);
            load_tile(buf + 40960, Bl + (size_t)(kt+1) * 64 * DH, 64, DH);
            CPA_COMMIT();
            CPA_WAIT(1);
        } else {
            CPA_WAIT(0);
        }
        __syncthreads();
        uint32_t buf = sbase + (kt & 1) * PV_STAGE;
        compute_ktile<1, true>(c, buf, buf + 16384, buf + 32768, buf + 40960,
                               m0, n0, lane);
        __syncthreads();
    }

#pragma unroll
    for (int nt = 0; nt < 8; nt++){
        int n = nt * 8 + (lane & 3) * 2;
#pragma unroll
        for (int half = 0; half < 2; half++){
            int m = bm + m0 + (lane >> 2) + half * 8;
            float* dst = out + ((size_t)z * SEQ + m) * DH + n;
            *(float2*)dst = make_float2(c[0][nt][half*2], c[0][nt][half*2+1]);
        }
    }
}

// ---------------------------------------------------------------------------
extern "C" void kernel_launch(void* const* d_in, const int* in_sizes, int n_in,
                              void* d_out, int out_size)
{
    const float* X  = (const float*)d_in[0];
    const float* Wq = (const float*)d_in[1];
    const float* Wk = (const float*)d_in[2];
    const float* Wv = (const float*)d_in[3];
    float* out = (float*)d_out;

    cudaFuncSetAttribute(k_qkv_mma,    cudaFuncAttributeMaxDynamicSharedMemorySize, QKV_SMEM);
    cudaFuncSetAttribute(k_scores_mma, cudaFuncAttributeMaxDynamicSharedMemorySize, SC_SMEM);
    cudaFuncSetAttribute(k_pv_mma,     cudaFuncAttributeMaxDynamicSharedMemorySize, PV_SMEM);

    k_splitX       <<<4096, 256>>>((const float4*)X);
    k_splitW       <<<dim3(32, 32, 3), dim3(32, 8)>>>(Wq, Wk, Wv);
    k_qkv_mma      <<<dim3(8, 32, 3), THR, QKV_SMEM>>>();
    k_scores_mma   <<<dim3(4, 16, HB), THR, SC_SMEM>>>();
    k_softmax_split<<<dim3(SEQ, HB), 256>>>();
    k_pv_mma       <<<dim3(16, HB), THR, PV_SMEM>>>(out);
}

// round 5
// speedup vs baseline: 2.8694x; 1.2040x over previous
#include <cuda_runtime.h>
#include <cuda_fp16.h>
#include <cstdint>

#define SEQ 2048
#define DIM 1024
#define DH  64
#define HB  32
#define NB  2
#define THR 256

// ---------------- scratch (static __device__, allocation-free) --------------
static __device__ __half g_Xh[4096*1024], g_Xl[4096*1024];
static __device__ __half g_Wth[3*1024*1024], g_Wtl[3*1024*1024];   // [z][n][k]
static __device__ __half g_Qh[HB*SEQ*DH], g_Ql[HB*SEQ*DH];         // [hb][s][dh]
static __device__ __half g_Kh[HB*SEQ*DH], g_Kl[HB*SEQ*DH];
static __device__ __half g_Vh[HB*SEQ*DH], g_Vl[HB*SEQ*DH];

// ---------------- helpers ---------------------------------------------------
__device__ __forceinline__ uint32_t s2u(const void* p){
    uint32_t a;
    asm("{ .reg .u64 t; cvta.to.shared.u64 t, %1; cvt.u32.u64 %0, t; }" : "=r"(a) : "l"(p));
    return a;
}
#define CPA(s,g) asm volatile("cp.async.cg.shared.global [%0], [%1], 16;" :: "r"(s), "l"(g))
#define CPA_COMMIT() asm volatile("cp.async.commit_group;" ::: "memory")
#define CPA_WAIT(n)  asm volatile("cp.async.wait_group %0;" :: "n"(n) : "memory")

__device__ __forceinline__ void ldsm4(uint32_t* r, uint32_t a){
    asm volatile("ldmatrix.sync.aligned.m8n8.x4.shared.b16 {%0,%1,%2,%3}, [%4];"
        : "=r"(r[0]), "=r"(r[1]), "=r"(r[2]), "=r"(r[3]) : "r"(a));
}
__device__ __forceinline__ void ldsm4t(uint32_t* r, uint32_t a){
    asm volatile("ldmatrix.sync.aligned.m8n8.x4.trans.shared.b16 {%0,%1,%2,%3}, [%4];"
        : "=r"(r[0]), "=r"(r[1]), "=r"(r[2]), "=r"(r[3]) : "r"(a));
}
__device__ __forceinline__ void mma16816(float* c, const uint32_t* a, uint32_t b0, uint32_t b1){
    asm volatile("mma.sync.aligned.m16n8k16.row.col.f32.f16.f16.f32 "
        "{%0,%1,%2,%3}, {%4,%5,%6,%7}, {%8,%9}, {%0,%1,%2,%3};"
        : "+f"(c[0]), "+f"(c[1]), "+f"(c[2]), "+f"(c[3])
        : "r"(a[0]), "r"(a[1]), "r"(a[2]), "r"(a[3]), "r"(b0), "r"(b1));
}
__device__ __forceinline__ uint32_t swa(uint32_t base, int r, int cb){
    uint32_t off = (uint32_t)r * 128u + (uint32_t)cb;
    return base + (off ^ ((off >> 3) & 0x70));
}
__device__ __forceinline__ void split2(float x, float y, uint32_t& hi, uint32_t& lo){
    __half hx = __float2half_rn(x), hy = __float2half_rn(y);
    __half lx = __float2half_rn(x - __half2float(hx));
    __half ly = __float2half_rn(y - __half2float(hy));
    __half2 H = __halves2half2(hx, hy), L = __halves2half2(lx, ly);
    hi = *(uint32_t*)&H; lo = *(uint32_t*)&L;
}
__device__ __forceinline__ void fsplit(float x, __half& h, __half& l){
    h = __float2half_rn(x);
    l = __float2half_rn(x - __half2float(h));
}
__device__ __forceinline__ void load_tile(uint32_t sdst, const __half* g,
                                          int rows, int gstride){
    for (int i = threadIdx.x; i < rows * 8; i += THR){
        int r = i >> 3, c = i & 7;
        uint32_t off = (uint32_t)r * 128u + (uint32_t)c * 16u;
        uint32_t sw  = off ^ ((off >> 3) & 0x70);
        CPA(sdst + sw, (const char*)(g + (size_t)r * gstride) + c * 16);
    }
}

// One 64-deep K-tile of split-fp16 NT GEMM for one warp (for QKV).
template<int WM>
__device__ __forceinline__ void compute_ktile(
    float (*c)[8][4], uint32_t sAh, uint32_t sAl, uint32_t sBh, uint32_t sBl,
    int m0, int n0, int lane)
{
#pragma unroll
    for (int kk = 0; kk < 4; kk++){
        uint32_t aH[WM][4], aL[WM][4];
#pragma unroll
        for (int mt = 0; mt < WM; mt++){
            int rr = m0 + mt * 16 + (lane & 15);
            int cb = kk * 32 + (lane >> 4) * 16;
            ldsm4(aH[mt], swa(sAh, rr, cb));
            ldsm4(aL[mt], swa(sAl, rr, cb));
        }
        uint32_t bH[4][4], bL[4][4];
#pragma unroll
        for (int nq = 0; nq < 4; nq++){
            int rr = n0 + nq * 16 + (lane & 15);
            int cb = kk * 32 + (lane >> 4) * 16;
            ldsm4(bH[nq], swa(sBh, rr, cb));
            ldsm4(bL[nq], swa(sBl, rr, cb));
        }
#pragma unroll
        for (int mt = 0; mt < WM; mt++)
#pragma unroll
            for (int nq = 0; nq < 4; nq++){
                mma16816(c[mt][2*nq],   aH[mt], bH[nq][0], bH[nq][2]);
                mma16816(c[mt][2*nq],   aH[mt], bL[nq][0], bL[nq][2]);
                mma16816(c[mt][2*nq],   aL[mt], bH[nq][0], bH[nq][2]);
                mma16816(c[mt][2*nq+1], aH[mt], bH[nq][1], bH[nq][3]);
                mma16816(c[mt][2*nq+1], aH[mt], bL[nq][1], bL[nq][3]);
                mma16816(c[mt][2*nq+1], aL[mt], bH[nq][1], bH[nq][3]);
            }
    }
}

// ---------------- prep ------------------------------------------------------
__global__ void __launch_bounds__(256) k_splitX(const float4* __restrict__ X){
    int i = blockIdx.x * 256 + threadIdx.x;
    float4 v = X[i];
    uint32_t h0, l0, h1, l1;
    split2(v.x, v.y, h0, l0);
    split2(v.z, v.w, h1, l1);
    ((uint2*)g_Xh)[i] = make_uint2(h0, h1);
    ((uint2*)g_Xl)[i] = make_uint2(l0, l1);
}

__global__ void __launch_bounds__(256) k_splitW(const float* __restrict__ Wq,
                                                const float* __restrict__ Wk,
                                                const float* __restrict__ Wv){
    const int z = blockIdx.z;
    const float* __restrict__ W = (z == 0) ? Wq : (z == 1) ? Wk : Wv;
    __shared__ float t[32][33];
    int tx = threadIdx.x, ty = threadIdx.y;      // (32,8)
    int bx = blockIdx.x * 32, by = blockIdx.y * 32;
#pragma unroll
    for (int i = 0; i < 32; i += 8)
        t[ty + i][tx] = W[(size_t)(by + ty + i) * DIM + bx + tx];
    __syncthreads();
#pragma unroll
    for (int i = 0; i < 32; i += 8){
        int n = bx + ty + i, k = by + tx;
        __half h, l; fsplit(t[tx][ty + i], h, l);
        size_t o = (size_t)z * DIM * DIM + (size_t)n * DIM + k;
        g_Wth[o] = h; g_Wtl[o] = l;
    }
}

// ---------------- QKV: X[4096,1024] @ Wt[N,K]^T -----------------------------
#define QKV_STAGE 65536
#define QKV_SMEM  (2 * QKV_STAGE)
__global__ void __launch_bounds__(THR) k_qkv_mma(){
    extern __shared__ __align__(1024) char smraw[];
    uint32_t sbase = s2u(smraw);
    const int tid = threadIdx.x, w = tid >> 5, lane = tid & 31;
    const int z  = blockIdx.z;
    const int bm = blockIdx.y * 128;
    const int bn = blockIdx.x * 128;

    const __half* Ah = g_Xh + (size_t)bm * DIM;
    const __half* Al = g_Xl + (size_t)bm * DIM;
    const __half* Bh = g_Wth + (size_t)z * DIM * DIM + (size_t)bn * DIM;
    const __half* Bl = g_Wtl + (size_t)z * DIM * DIM + (size_t)bn * DIM;

    float c[2][8][4];
#pragma unroll
    for (int a = 0; a < 2; a++)
#pragma unroll
        for (int b = 0; b < 8; b++)
#pragma unroll
            for (int d = 0; d < 4; d++) c[a][b][d] = 0.f;

    const int m0 = (w >> 1) * 32, n0 = (w & 1) * 64;
    const int NT = DIM / 64;   // 16

    {
        uint32_t buf = sbase;
        load_tile(buf,         Ah, 128, DIM);
        load_tile(buf + 16384, Al, 128, DIM);
        load_tile(buf + 32768, Bh, 128, DIM);
        load_tile(buf + 49152, Bl, 128, DIM);
        CPA_COMMIT();
    }
    for (int kt = 0; kt < NT; kt++){
        if (kt + 1 < NT){
            uint32_t buf = sbase + ((kt + 1) & 1) * QKV_STAGE;
            load_tile(buf,         Ah + (kt+1) * 64, 128, DIM);
            load_tile(buf + 16384, Al + (kt+1) * 64, 128, DIM);
            load_tile(buf + 32768, Bh + (kt+1) * 64, 128, DIM);
            load_tile(buf + 49152, Bl + (kt+1) * 64, 128, DIM);
            CPA_COMMIT();
            CPA_WAIT(1);
        } else {
            CPA_WAIT(0);
        }
        __syncthreads();
        uint32_t buf = sbase + (kt & 1) * QKV_STAGE;
        compute_ktile<2>(c, buf, buf + 16384, buf + 32768, buf + 49152,
                         m0, n0, lane);
        __syncthreads();
    }

    const float sc = (z == 0) ? 0.125f : 1.0f;
    __half* Gh = (z == 0) ? g_Qh : (z == 1) ? g_Kh : g_Vh;
    __half* Gl = (z == 0) ? g_Ql : (z == 1) ? g_Kl : g_Vl;
#pragma unroll
    for (int mt = 0; mt < 2; mt++){
#pragma unroll
        for (int nt = 0; nt < 8; nt++){
            int n = bn + n0 + nt * 8 + (lane & 3) * 2;
            int h = n >> 6, d = n & 63;
#pragma unroll
            for (int half = 0; half < 2; half++){
                int m = bm + m0 + mt * 16 + (lane >> 2) + half * 8;
                int bb = m >> 11, s = m & (SEQ - 1);
                size_t o = ((size_t)(h * NB + bb) * SEQ + s) * DH + d;
                uint32_t hi, lo;
                split2(c[mt][nt][half*2] * sc, c[mt][nt][half*2+1] * sc, hi, lo);
                *(uint32_t*)(Gh + o) = hi;
                *(uint32_t*)(Gl + o) = lo;
            }
        }
    }
}

// ---------------- fused flash attention -------------------------------------
// Per CTA: 128 q rows (8 warps x 16), loop over 16 k-tiles of 128 keys.
// SMEM: Q hi/lo 32KB resident + 2 stages x (K hi/lo + V hi/lo = 64KB) = 160KB.
#define FA_STAGE 65536
#define FA_SMEM  (32768 + 2 * FA_STAGE)
__global__ void __launch_bounds__(THR) k_flash(float* __restrict__ out){
    extern __shared__ __align__(1024) char smraw[];
    uint32_t sbase = s2u(smraw);
    const int tid = threadIdx.x, w = tid >> 5, lane = tid & 31;
    const int z  = blockIdx.y;
    const int bm = blockIdx.x * 128;

    const uint32_t sQh = sbase, sQl = sbase + 16384;
    const uint32_t stg = sbase + 32768;

    const __half* Kh = g_Kh + (size_t)z * SEQ * DH;
    const __half* Kl = g_Kl + (size_t)z * SEQ * DH;
    const __half* Vh = g_Vh + (size_t)z * SEQ * DH;
    const __half* Vl = g_Vl + (size_t)z * SEQ * DH;

    // prologue: Q + stage 0 in one commit group
    load_tile(sQh, g_Qh + ((size_t)z * SEQ + bm) * DH, 128, DH);
    load_tile(sQl, g_Ql + ((size_t)z * SEQ + bm) * DH, 128, DH);
    load_tile(stg,         Kh, 128, DH);
    load_tile(stg + 16384, Kl, 128, DH);
    load_tile(stg + 32768, Vh, 128, DH);
    load_tile(stg + 49152, Vl, 128, DH);
    CPA_COMMIT();

    uint32_t qH[4][4], qL[4][4];
    float co[8][4];
#pragma unroll
    for (int i = 0; i < 8; i++)
#pragma unroll
        for (int j = 0; j < 4; j++) co[i][j] = 0.f;
    float m0 = -1e30f, m1 = -1e30f, l0 = 0.f, l1 = 0.f;

    const int NT = SEQ / 128;   // 16
    for (int kt = 0; kt < NT; kt++){
        if (kt + 1 < NT){
            uint32_t buf = stg + ((kt + 1) & 1) * FA_STAGE;
            load_tile(buf,         Kh + (size_t)(kt+1) * 128 * DH, 128, DH);
            load_tile(buf + 16384, Kl + (size_t)(kt+1) * 128 * DH, 128, DH);
            load_tile(buf + 32768, Vh + (size_t)(kt+1) * 128 * DH, 128, DH);
            load_tile(buf + 49152, Vl + (size_t)(kt+1) * 128 * DH, 128, DH);
            CPA_COMMIT();
            CPA_WAIT(1);
        } else {
            CPA_WAIT(0);
        }
        __syncthreads();

        if (kt == 0){
#pragma unroll
            for (int kk = 0; kk < 4; kk++){
                int rr = w * 16 + (lane & 15);
                int cb = kk * 32 + (lane >> 4) * 16;
                ldsm4(qH[kk], swa(sQh, rr, cb));
                ldsm4(qL[kk], swa(sQl, rr, cb));
            }
        }

        uint32_t buf = stg + (kt & 1) * FA_STAGE;
        const uint32_t sKh = buf, sKl = buf + 16384;
        const uint32_t sVh = buf + 32768, sVl = buf + 49152;

        // ---- S = Q @ K^T  (16 q-rows x 128 keys per warp) ----
        float cs[16][4];
#pragma unroll
        for (int t = 0; t < 16; t++)
#pragma unroll
            for (int j = 0; j < 4; j++) cs[t][j] = 0.f;
#pragma unroll
        for (int kk = 0; kk < 4; kk++){
#pragma unroll
            for (int nq = 0; nq < 8; nq++){
                uint32_t bH[4], bL[4];
                int rr = nq * 16 + (lane & 15);
                int cb = kk * 32 + (lane >> 4) * 16;
                ldsm4(bH, swa(sKh, rr, cb));
                ldsm4(bL, swa(sKl, rr, cb));
                mma16816(cs[2*nq],   qH[kk], bH[0], bH[2]);
                mma16816(cs[2*nq],   qH[kk], bL[0], bL[2]);
                mma16816(cs[2*nq],   qL[kk], bH[0], bH[2]);
                mma16816(cs[2*nq+1], qH[kk], bH[1], bH[3]);
                mma16816(cs[2*nq+1], qH[kk], bL[1], bL[3]);
                mma16816(cs[2*nq+1], qL[kk], bH[1], bH[3]);
            }
        }

        // ---- online softmax (rows r0=lane>>2, r1=r0+8) ----
        float mx0 = -1e30f, mx1 = -1e30f;
#pragma unroll
        for (int t = 0; t < 16; t++){
            mx0 = fmaxf(mx0, fmaxf(cs[t][0], cs[t][1]));
            mx1 = fmaxf(mx1, fmaxf(cs[t][2], cs[t][3]));
        }
        mx0 = fmaxf(mx0, __shfl_xor_sync(0xffffffffu, mx0, 1));
        mx0 = fmaxf(mx0, __shfl_xor_sync(0xffffffffu, mx0, 2));
        mx1 = fmaxf(mx1, __shfl_xor_sync(0xffffffffu, mx1, 1));
        mx1 = fmaxf(mx1, __shfl_xor_sync(0xffffffffu, mx1, 2));

        float mn0 = fmaxf(m0, mx0), mn1 = fmaxf(m1, mx1);
        float sc0 = __expf(m0 - mn0), sc1 = __expf(m1 - mn1);
        m0 = mn0; m1 = mn1;

        float sum0 = 0.f, sum1 = 0.f;
#pragma unroll
        for (int t = 0; t < 16; t++){
            cs[t][0] = __expf(cs[t][0] - m0);
            cs[t][1] = __expf(cs[t][1] - m0);
            cs[t][2] = __expf(cs[t][2] - m1);
            cs[t][3] = __expf(cs[t][3] - m1);
            sum0 += cs[t][0] + cs[t][1];
            sum1 += cs[t][2] + cs[t][3];
        }
        // FULL row sums: reduce across the thread quad (bits 0-1 of lane)
        sum0 += __shfl_xor_sync(0xffffffffu, sum0, 1);
        sum0 += __shfl_xor_sync(0xffffffffu, sum0, 2);
        sum1 += __shfl_xor_sync(0xffffffffu, sum1, 1);
        sum1 += __shfl_xor_sync(0xffffffffu, sum1, 2);
        l0 = l0 * sc0 + sum0;
        l1 = l1 * sc1 + sum1;
#pragma unroll
        for (int nt = 0; nt < 8; nt++){
            co[nt][0] *= sc0; co[nt][1] *= sc0;
            co[nt][2] *= sc1; co[nt][3] *= sc1;
        }

        // ---- O += P @ V ----
#pragma unroll
        for (int kc = 0; kc < 8; kc++){
            uint32_t aH[4], aL[4];
            split2(cs[2*kc][0],   cs[2*kc][1],   aH[0], aL[0]);
            split2(cs[2*kc][2],   cs[2*kc][3],   aH[1], aL[1]);
            split2(cs[2*kc+1][0], cs[2*kc+1][1], aH[2], aL[2]);
            split2(cs[2*kc+1][2], cs[2*kc+1][3], aH[3], aL[3]);
#pragma unroll
            for (int nq = 0; nq < 4; nq++){
                uint32_t bH[4], bL[4];
                int rr = kc * 16 + ((lane >> 4) & 1) * 8 + (lane & 7);
                int cb = (nq * 16 + ((lane >> 3) & 1) * 8) * 2;
                ldsm4t(bH, swa(sVh, rr, cb));
                ldsm4t(bL, swa(sVl, rr, cb));
                mma16816(co[2*nq],   aH, bH[0], bH[2]);
                mma16816(co[2*nq],   aH, bL[0], bL[2]);
                mma16816(co[2*nq],   aL, bH[0], bH[2]);
                mma16816(co[2*nq+1], aH, bH[1], bH[3]);
                mma16816(co[2*nq+1], aH, bL[1], bL[3]);
                mma16816(co[2*nq+1], aL, bH[1], bH[3]);
            }
        }
        __syncthreads();
    }

    // ---- epilogue ----
    const float inv0 = 1.f / l0, inv1 = 1.f / l1;
    const int r0 = bm + w * 16 + (lane >> 2);
#pragma unroll
    for (int nt = 0; nt < 8; nt++){
        int n = nt * 8 + (lane & 3) * 2;
        float* d0 = out + ((size_t)z * SEQ + r0) * DH + n;
        float* d1 = out + ((size_t)z * SEQ + r0 + 8) * DH + n;
        *(float2*)d0 = make_float2(co[nt][0] * inv0, co[nt][1] * inv0);
        *(float2*)d1 = make_float2(co[nt][2] * inv1, co[nt][3] * inv1);
    }
}

// ---------------------------------------------------------------------------
extern "C" void kernel_launch(void* const* d_in, const int* in_sizes, int n_in,
                              void* d_out, int out_size)
{
    const float* X  = (const float*)d_in[0];
    const float* Wq = (const float*)d_in[1];
    const float* Wk = (const float*)d_in[2];
    const float* Wv = (const float*)d_in[3];
    float* out = (float*)d_out;

    cudaFuncSetAttribute(k_qkv_mma, cudaFuncAttributeMaxDynamicSharedMemorySize, QKV_SMEM);
    cudaFuncSetAttribute(k_flash,   cudaFuncAttributeMaxDynamicSharedMemorySize, FA_SMEM);

    k_splitX <<<4096, 256>>>((const float4*)X);
    k_splitW <<<dim3(32, 32, 3), dim3(32, 8)>>>(Wq, Wk, Wv);
    k_qkv_mma<<<dim3(8, 32, 3), THR, QKV_SMEM>>>();
    k_flash  <<<dim3(SEQ / 128, HB), THR, FA_SMEM>>>(out);
}

// round 6
// speedup vs baseline: 3.0064x; 1.0477x over previous
#include <cuda_runtime.h>
#include <cuda_fp16.h>
#include <cstdint>

#define SEQ 2048
#define DIM 1024
#define DH  64
#define HB  32
#define NB  2
#define THR 512

// ---------------- scratch (static __device__, allocation-free) --------------
static __device__ __half g_Xh[4096*1024], g_Xl[4096*1024];
static __device__ __half g_Wth[3*1024*1024], g_Wtl[3*1024*1024];   // [z][n][k]
static __device__ __half g_Qh[HB*SEQ*DH], g_Ql[HB*SEQ*DH];         // [hb][s][dh]
static __device__ __half g_Kh[HB*SEQ*DH], g_Kl[HB*SEQ*DH];
static __device__ __half g_Vh[HB*SEQ*DH], g_Vl[HB*SEQ*DH];

// ---------------- helpers ---------------------------------------------------
__device__ __forceinline__ uint32_t s2u(const void* p){
    uint32_t a;
    asm("{ .reg .u64 t; cvta.to.shared.u64 t, %1; cvt.u32.u64 %0, t; }" : "=r"(a) : "l"(p));
    return a;
}
#define CPA(s,g) asm volatile("cp.async.cg.shared.global [%0], [%1], 16;" :: "r"(s), "l"(g))
#define CPA_COMMIT() asm volatile("cp.async.commit_group;" ::: "memory")
#define CPA_WAIT(n)  asm volatile("cp.async.wait_group %0;" :: "n"(n) : "memory")

__device__ __forceinline__ void ldsm4(uint32_t* r, uint32_t a){
    asm volatile("ldmatrix.sync.aligned.m8n8.x4.shared.b16 {%0,%1,%2,%3}, [%4];"
        : "=r"(r[0]), "=r"(r[1]), "=r"(r[2]), "=r"(r[3]) : "r"(a));
}
__device__ __forceinline__ void ldsm4t(uint32_t* r, uint32_t a){
    asm volatile("ldmatrix.sync.aligned.m8n8.x4.trans.shared.b16 {%0,%1,%2,%3}, [%4];"
        : "=r"(r[0]), "=r"(r[1]), "=r"(r[2]), "=r"(r[3]) : "r"(a));
}
__device__ __forceinline__ void mma16816(float* c, const uint32_t* a, uint32_t b0, uint32_t b1){
    asm volatile("mma.sync.aligned.m16n8k16.row.col.f32.f16.f16.f32 "
        "{%0,%1,%2,%3}, {%4,%5,%6,%7}, {%8,%9}, {%0,%1,%2,%3};"
        : "+f"(c[0]), "+f"(c[1]), "+f"(c[2]), "+f"(c[3])
        : "r"(a[0]), "r"(a[1]), "r"(a[2]), "r"(a[3]), "r"(b0), "r"(b1));
}
__device__ __forceinline__ uint32_t swa(uint32_t base, int r, int cb){
    uint32_t off = (uint32_t)r * 128u + (uint32_t)cb;
    return base + (off ^ ((off >> 3) & 0x70));
}
__device__ __forceinline__ void split2(float x, float y, uint32_t& hi, uint32_t& lo){
    __half hx = __float2half_rn(x), hy = __float2half_rn(y);
    __half lx = __float2half_rn(x - __half2float(hx));
    __half ly = __float2half_rn(y - __half2float(hy));
    __half2 H = __halves2half2(hx, hy), L = __halves2half2(lx, ly);
    hi = *(uint32_t*)&H; lo = *(uint32_t*)&L;
}
__device__ __forceinline__ void fsplit(float x, __half& h, __half& l){
    h = __float2half_rn(x);
    l = __float2half_rn(x - __half2float(h));
}
__device__ __forceinline__ void load_tile(uint32_t sdst, const __half* g,
                                          int rows, int gstride){
    for (int i = threadIdx.x; i < rows * 8; i += THR){
        int r = i >> 3, c = i & 7;
        uint32_t off = (uint32_t)r * 128u + (uint32_t)c * 16u;
        uint32_t sw  = off ^ ((off >> 3) & 0x70);
        CPA(sdst + sw, (const char*)(g + (size_t)r * gstride) + c * 16);
    }
}

// One 64-deep K-tile of split-fp16 NT GEMM for one warp (for QKV), 16x64 tile.
__device__ __forceinline__ void compute_ktile1(
    float (*c)[4], uint32_t sAh, uint32_t sAl, uint32_t sBh, uint32_t sBl,
    int m0, int n0, int lane)
{
#pragma unroll
    for (int kk = 0; kk < 4; kk++){
        uint32_t aH[4], aL[4];
        {
            int rr = m0 + (lane & 15);
            int cb = kk * 32 + (lane >> 4) * 16;
            ldsm4(aH, swa(sAh, rr, cb));
            ldsm4(aL, swa(sAl, rr, cb));
        }
#pragma unroll
        for (int nq = 0; nq < 4; nq++){
            uint32_t bH[4], bL[4];
            int rr = n0 + nq * 16 + (lane & 15);
            int cb = kk * 32 + (lane >> 4) * 16;
            ldsm4(bH, swa(sBh, rr, cb));
            ldsm4(bL, swa(sBl, rr, cb));
            mma16816(c[2*nq],   aH, bH[0], bH[2]);
            mma16816(c[2*nq],   aH, bL[0], bL[2]);
            mma16816(c[2*nq],   aL, bH[0], bH[2]);
            mma16816(c[2*nq+1], aH, bH[1], bH[3]);
            mma16816(c[2*nq+1], aH, bL[1], bL[3]);
            mma16816(c[2*nq+1], aL, bH[1], bH[3]);
        }
    }
}

// ---------------- prep ------------------------------------------------------
__global__ void __launch_bounds__(256) k_splitX(const float4* __restrict__ X){
    int i = blockIdx.x * 256 + threadIdx.x;
    float4 v = X[i];
    uint32_t h0, l0, h1, l1;
    split2(v.x, v.y, h0, l0);
    split2(v.z, v.w, h1, l1);
    ((uint2*)g_Xh)[i] = make_uint2(h0, h1);
    ((uint2*)g_Xl)[i] = make_uint2(l0, l1);
}

__global__ void __launch_bounds__(256) k_splitW(const float* __restrict__ Wq,
                                                const float* __restrict__ Wk,
                                                const float* __restrict__ Wv){
    const int z = blockIdx.z;
    const float* __restrict__ W = (z == 0) ? Wq : (z == 1) ? Wk : Wv;
    __shared__ float t[32][33];
    int tx = threadIdx.x, ty = threadIdx.y;      // (32,8)
    int bx = blockIdx.x * 32, by = blockIdx.y * 32;
#pragma unroll
    for (int i = 0; i < 32; i += 8)
        t[ty + i][tx] = W[(size_t)(by + ty + i) * DIM + bx + tx];
    __syncthreads();
#pragma unroll
    for (int i = 0; i < 32; i += 8){
        int n = bx + ty + i, k = by + tx;
        __half h, l; fsplit(t[tx][ty + i], h, l);
        size_t o = (size_t)z * DIM * DIM + (size_t)n * DIM + k;
        g_Wth[o] = h; g_Wtl[o] = l;
    }
}

// ---------------- QKV: X[4096,1024] @ Wt[N,K]^T, 16 warps -------------------
#define QKV_STAGE 65536
#define QKV_SMEM  (2 * QKV_STAGE)
__global__ void __launch_bounds__(THR) k_qkv_mma(){
    extern __shared__ __align__(1024) char smraw[];
    uint32_t sbase = s2u(smraw);
    const int tid = threadIdx.x, w = tid >> 5, lane = tid & 31;
    const int z  = blockIdx.z;
    const int bm = blockIdx.y * 128;
    const int bn = blockIdx.x * 128;

    const __half* Ah = g_Xh + (size_t)bm * DIM;
    const __half* Al = g_Xl + (size_t)bm * DIM;
    const __half* Bh = g_Wth + (size_t)z * DIM * DIM + (size_t)bn * DIM;
    const __half* Bl = g_Wtl + (size_t)z * DIM * DIM + (size_t)bn * DIM;

    float c[8][4];
#pragma unroll
    for (int b = 0; b < 8; b++)
#pragma unroll
        for (int d = 0; d < 4; d++) c[b][d] = 0.f;

    const int m0 = (w & 7) * 16, n0 = (w >> 3) * 64;
    const int NT = DIM / 64;   // 16

    {
        uint32_t buf = sbase;
        load_tile(buf,         Ah, 128, DIM);
        load_tile(buf + 16384, Al, 128, DIM);
        load_tile(buf + 32768, Bh, 128, DIM);
        load_tile(buf + 49152, Bl, 128, DIM);
        CPA_COMMIT();
    }
    for (int kt = 0; kt < NT; kt++){
        if (kt + 1 < NT){
            uint32_t buf = sbase + ((kt + 1) & 1) * QKV_STAGE;
            load_tile(buf,         Ah + (kt+1) * 64, 128, DIM);
            load_tile(buf + 16384, Al + (kt+1) * 64, 128, DIM);
            load_tile(buf + 32768, Bh + (kt+1) * 64, 128, DIM);
            load_tile(buf + 49152, Bl + (kt+1) * 64, 128, DIM);
            CPA_COMMIT();
            CPA_WAIT(1);
        } else {
            CPA_WAIT(0);
        }
        __syncthreads();
        uint32_t buf = sbase + (kt & 1) * QKV_STAGE;
        compute_ktile1(c, buf, buf + 16384, buf + 32768, buf + 49152,
                       m0, n0, lane);
        __syncthreads();
    }

    // Q gets 0.125 * log2(e) so flash can use exp2 directly.
    const float sc = (z == 0) ? 0.125f * 1.4426950408889634f : 1.0f;
    __half* Gh = (z == 0) ? g_Qh : (z == 1) ? g_Kh : g_Vh;
    __half* Gl = (z == 0) ? g_Ql : (z == 1) ? g_Kl : g_Vl;
#pragma unroll
    for (int nt = 0; nt < 8; nt++){
        int n = bn + n0 + nt * 8 + (lane & 3) * 2;
        int h = n >> 6, d = n & 63;
#pragma unroll
        for (int half = 0; half < 2; half++){
            int m = bm + m0 + (lane >> 2) + half * 8;
            int bb = m >> 11, s = m & (SEQ - 1);
            size_t o = ((size_t)(h * NB + bb) * SEQ + s) * DH + d;
            uint32_t hi, lo;
            split2(c[nt][half*2] * sc, c[nt][half*2+1] * sc, hi, lo);
            *(uint32_t*)(Gh + o) = hi;
            *(uint32_t*)(Gl + o) = lo;
        }
    }
}

// ---------------- fused flash attention, 16 warps key-split -----------------
// Per CTA: 128 q rows; warp (wq,wg): q rows [wq*16,+16), keys [wg*64,+64) of
// each staged 128-key tile. Private (m,l,O) per warp; split-K merge at end.
#define FA_STAGE 65536
#define FA_SMEM  (32768 + 2 * FA_STAGE)
__global__ void __launch_bounds__(THR) k_flash(float* __restrict__ out){
    extern __shared__ __align__(1024) char smraw[];
    uint32_t sbase = s2u(smraw);
    const int tid = threadIdx.x, w = tid >> 5, lane = tid & 31;
    const int wq = w & 7, wg = w >> 3;
    const int z  = blockIdx.y;
    const int bm = blockIdx.x * 128;

    const uint32_t sQh = sbase, sQl = sbase + 16384;
    const uint32_t stg = sbase + 32768;

    const __half* Kh = g_Kh + (size_t)z * SEQ * DH;
    const __half* Kl = g_Kl + (size_t)z * SEQ * DH;
    const __half* Vh = g_Vh + (size_t)z * SEQ * DH;
    const __half* Vl = g_Vl + (size_t)z * SEQ * DH;

    // prologue: Q + stage 0
    load_tile(sQh, g_Qh + ((size_t)z * SEQ + bm) * DH, 128, DH);
    load_tile(sQl, g_Ql + ((size_t)z * SEQ + bm) * DH, 128, DH);
    load_tile(stg,         Kh, 128, DH);
    load_tile(stg + 16384, Kl, 128, DH);
    load_tile(stg + 32768, Vh, 128, DH);
    load_tile(stg + 49152, Vl, 128, DH);
    CPA_COMMIT();

    float co[8][4];
#pragma unroll
    for (int i = 0; i < 8; i++)
#pragma unroll
        for (int j = 0; j < 4; j++) co[i][j] = 0.f;
    float m0 = -1e30f, m1 = -1e30f, l0 = 0.f, l1 = 0.f;

    const int NT = SEQ / 128;   // 16
    for (int kt = 0; kt < NT; kt++){
        if (kt + 1 < NT){
            uint32_t buf = stg + ((kt + 1) & 1) * FA_STAGE;
            load_tile(buf,         Kh + (size_t)(kt+1) * 128 * DH, 128, DH);
            load_tile(buf + 16384, Kl + (size_t)(kt+1) * 128 * DH, 128, DH);
            load_tile(buf + 32768, Vh + (size_t)(kt+1) * 128 * DH, 128, DH);
            load_tile(buf + 49152, Vl + (size_t)(kt+1) * 128 * DH, 128, DH);
            CPA_COMMIT();
            CPA_WAIT(1);
        } else {
            CPA_WAIT(0);
        }
        __syncthreads();

        uint32_t buf = stg + (kt & 1) * FA_STAGE;
        const uint32_t sKh = buf, sKl = buf + 16384;
        const uint32_t sVh = buf + 32768, sVl = buf + 49152;

        // ---- S = Q @ K^T  (16 q-rows x 64 keys per warp) ----
        float cs[8][4];
#pragma unroll
        for (int t = 0; t < 8; t++)
#pragma unroll
            for (int j = 0; j < 4; j++) cs[t][j] = 0.f;
#pragma unroll
        for (int kk = 0; kk < 4; kk++){
            uint32_t qH[4], qL[4];
            {
                int rr = wq * 16 + (lane & 15);
                int cb = kk * 32 + (lane >> 4) * 16;
                ldsm4(qH, swa(sQh, rr, cb));
                ldsm4(qL, swa(sQl, rr, cb));
            }
#pragma unroll
            for (int nq = 0; nq < 4; nq++){
                uint32_t bH[4], bL[4];
                int rr = wg * 64 + nq * 16 + (lane & 15);
                int cb = kk * 32 + (lane >> 4) * 16;
                ldsm4(bH, swa(sKh, rr, cb));
                ldsm4(bL, swa(sKl, rr, cb));
                mma16816(cs[2*nq],   qH, bH[0], bH[2]);
                mma16816(cs[2*nq],   qH, bL[0], bL[2]);
                mma16816(cs[2*nq],   qL, bH[0], bH[2]);
                mma16816(cs[2*nq+1], qH, bH[1], bH[3]);
                mma16816(cs[2*nq+1], qH, bL[1], bL[3]);
                mma16816(cs[2*nq+1], qL, bH[1], bH[3]);
            }
        }

        // ---- online softmax in base-2 (rows r0=lane>>2, r1=r0+8) ----
        float mx0 = -1e30f, mx1 = -1e30f;
#pragma unroll
        for (int t = 0; t < 8; t++){
            mx0 = fmaxf(mx0, fmaxf(cs[t][0], cs[t][1]));
            mx1 = fmaxf(mx1, fmaxf(cs[t][2], cs[t][3]));
        }
        mx0 = fmaxf(mx0, __shfl_xor_sync(0xffffffffu, mx0, 1));
        mx0 = fmaxf(mx0, __shfl_xor_sync(0xffffffffu, mx0, 2));
        mx1 = fmaxf(mx1, __shfl_xor_sync(0xffffffffu, mx1, 1));
        mx1 = fmaxf(mx1, __shfl_xor_sync(0xffffffffu, mx1, 2));

        float mn0 = fmaxf(m0, mx0), mn1 = fmaxf(m1, mx1);
        float sc0 = exp2f(m0 - mn0), sc1 = exp2f(m1 - mn1);
        m0 = mn0; m1 = mn1;

        float sum0 = 0.f, sum1 = 0.f;
#pragma unroll
        for (int t = 0; t < 8; t++){
            cs[t][0] = exp2f(cs[t][0] - m0);
            cs[t][1] = exp2f(cs[t][1] - m0);
            cs[t][2] = exp2f(cs[t][2] - m1);
            cs[t][3] = exp2f(cs[t][3] - m1);
            sum0 += cs[t][0] + cs[t][1];
            sum1 += cs[t][2] + cs[t][3];
        }
        sum0 += __shfl_xor_sync(0xffffffffu, sum0, 1);
        sum0 += __shfl_xor_sync(0xffffffffu, sum0, 2);
        sum1 += __shfl_xor_sync(0xffffffffu, sum1, 1);
        sum1 += __shfl_xor_sync(0xffffffffu, sum1, 2);
        l0 = l0 * sc0 + sum0;
        l1 = l1 * sc1 + sum1;
#pragma unroll
        for (int nt = 0; nt < 8; nt++){
            co[nt][0] *= sc0; co[nt][1] *= sc0;
            co[nt][2] *= sc1; co[nt][3] *= sc1;
        }

        // ---- O += P @ V (keys wg*64..+64) ----
#pragma unroll
        for (int kc = 0; kc < 4; kc++){
            uint32_t aH[4], aL[4];
            split2(cs[2*kc][0],   cs[2*kc][1],   aH[0], aL[0]);
            split2(cs[2*kc][2],   cs[2*kc][3],   aH[1], aL[1]);
            split2(cs[2*kc+1][0], cs[2*kc+1][1], aH[2], aL[2]);
            split2(cs[2*kc+1][2], cs[2*kc+1][3], aH[3], aL[3]);
#pragma unroll
            for (int nq = 0; nq < 4; nq++){
                uint32_t bH[4], bL[4];
                int rr = wg * 64 + kc * 16 + ((lane >> 4) & 1) * 8 + (lane & 7);
                int cb = (nq * 16 + ((lane >> 3) & 1) * 8) * 2;
                ldsm4t(bH, swa(sVh, rr, cb));
                ldsm4t(bL, swa(sVl, rr, cb));
                mma16816(co[2*nq],   aH, bH[0], bH[2]);
                mma16816(co[2*nq],   aH, bL[0], bL[2]);
                mma16816(co[2*nq],   aL, bH[0], bH[2]);
                mma16816(co[2*nq+1], aH, bH[1], bH[3]);
                mma16816(co[2*nq+1], aH, bL[1], bL[3]);
                mma16816(co[2*nq+1], aL, bH[1], bH[3]);
            }
        }
        __syncthreads();
    }

    // ---- split-K merge across wg pairs (exchange via smem) ----
    float* ex = (float*)smraw;
    float* p = ex + ((size_t)(wq * 32 + lane)) * 37;
    if (wg == 1){
#pragma unroll
        for (int i = 0; i < 8; i++)
#pragma unroll
            for (int j = 0; j < 4; j++) p[i*4 + j] = co[i][j];
        p[32] = m0; p[33] = m1; p[34] = l0; p[35] = l1;
    }
    __syncthreads();
    if (wg == 0){
        float m0b = p[32], m1b = p[33], l0b = p[34], l1b = p[35];
        float mm0 = fmaxf(m0, m0b), mm1 = fmaxf(m1, m1b);
        float a0 = exp2f(m0 - mm0), b0 = exp2f(m0b - mm0);
        float a1 = exp2f(m1 - mm1), b1 = exp2f(m1b - mm1);
        float inv0 = 1.f / (l0 * a0 + l0b * b0);
        float inv1 = 1.f / (l1 * a1 + l1b * b1);

        const int r0 = bm + wq * 16 + (lane >> 2);
#pragma unroll
        for (int nt = 0; nt < 8; nt++){
            int n = nt * 8 + (lane & 3) * 2;
            float* d0 = out + ((size_t)z * SEQ + r0) * DH + n;
            float* d1 = out + ((size_t)z * SEQ + r0 + 8) * DH + n;
            float o00 = (co[nt][0] * a0 + p[nt*4+0] * b0) * inv0;
            float o01 = (co[nt][1] * a0 + p[nt*4+1] * b0) * inv0;
            float o10 = (co[nt][2] * a1 + p[nt*4+2] * b1) * inv1;
            float o11 = (co[nt][3] * a1 + p[nt*4+3] * b1) * inv1;
            *(float2*)d0 = make_float2(o00, o01);
            *(float2*)d1 = make_float2(o10, o11);
        }
    }
}

// ---------------------------------------------------------------------------
extern "C" void kernel_launch(void* const* d_in, const int* in_sizes, int n_in,
                              void* d_out, int out_size)
{
    const float* X  = (const float*)d_in[0];
    const float* Wq = (const float*)d_in[1];
    const float* Wk = (const float*)d_in[2];
    const float* Wv = (const float*)d_in[3];
    float* out = (float*)d_out;

    cudaFuncSetAttribute(k_qkv_mma, cudaFuncAttributeMaxDynamicSharedMemorySize, QKV_SMEM);
    cudaFuncSetAttribute(k_flash,   cudaFuncAttributeMaxDynamicSharedMemorySize, FA_SMEM);

    k_splitX <<<4096, 256>>>((const float4*)X);
    k_splitW <<<dim3(32, 32, 3), dim3(32, 8)>>>(Wq, Wk, Wv);
    k_qkv_mma<<<dim3(8, 32, 3), THR, QKV_SMEM>>>();
    k_flash  <<<dim3(SEQ / 128, HB), THR, FA_SMEM>>>(out);
}

// round 7
// speedup vs baseline: 3.3578x; 1.1169x over previous
#include <cuda_runtime.h>
#include <cuda_fp16.h>
#include <cstdint>

#define SEQ 2048
#define DIM 1024
#define DH  64
#define HB  32
#define NB  2
#define THR 512

// ---------------- scratch (static __device__, allocation-free) --------------
static __device__ __half g_Xh[4096*1024], g_Xl[4096*1024];
static __device__ __half g_Wth[3*1024*1024], g_Wtl[3*1024*1024];   // [z][n][k]
static __device__ __half g_Qh[HB*SEQ*DH], g_Ql[HB*SEQ*DH];         // [hb][s][dh]
static __device__ __half g_Kh[HB*SEQ*DH], g_Kl[HB*SEQ*DH];
static __device__ __half g_Vh[HB*SEQ*DH], g_Vl[HB*SEQ*DH];

// ---------------- helpers ---------------------------------------------------
__device__ __forceinline__ uint32_t s2u(const void* p){
    uint32_t a;
    asm("{ .reg .u64 t; cvta.to.shared.u64 t, %1; cvt.u32.u64 %0, t; }" : "=r"(a) : "l"(p));
    return a;
}
#define CPA(s,g) asm volatile("cp.async.cg.shared.global [%0], [%1], 16;" :: "r"(s), "l"(g))
#define CPA_COMMIT() asm volatile("cp.async.commit_group;" ::: "memory")
#define CPA_WAIT(n)  asm volatile("cp.async.wait_group %0;" :: "n"(n) : "memory")

__device__ __forceinline__ void ldsm4(uint32_t* r, uint32_t a){
    asm volatile("ldmatrix.sync.aligned.m8n8.x4.shared.b16 {%0,%1,%2,%3}, [%4];"
        : "=r"(r[0]), "=r"(r[1]), "=r"(r[2]), "=r"(r[3]) : "r"(a));
}
__device__ __forceinline__ void ldsm4t(uint32_t* r, uint32_t a){
    asm volatile("ldmatrix.sync.aligned.m8n8.x4.trans.shared.b16 {%0,%1,%2,%3}, [%4];"
        : "=r"(r[0]), "=r"(r[1]), "=r"(r[2]), "=r"(r[3]) : "r"(a));
}
__device__ __forceinline__ void mma16816(float* c, const uint32_t* a, uint32_t b0, uint32_t b1){
    asm volatile("mma.sync.aligned.m16n8k16.row.col.f32.f16.f16.f32 "
        "{%0,%1,%2,%3}, {%4,%5,%6,%7}, {%8,%9}, {%0,%1,%2,%3};"
        : "+f"(c[0]), "+f"(c[1]), "+f"(c[2]), "+f"(c[3])
        : "r"(a[0]), "r"(a[1]), "r"(a[2]), "r"(a[3]), "r"(b0), "r"(b1));
}
__device__ __forceinline__ uint32_t swa(uint32_t base, int r, int cb){
    uint32_t off = (uint32_t)r * 128u + (uint32_t)cb;
    return base + (off ^ ((off >> 3) & 0x70));
}
__device__ __forceinline__ void split2(float x, float y, uint32_t& hi, uint32_t& lo){
    __half hx = __float2half_rn(x), hy = __float2half_rn(y);
    __half lx = __float2half_rn(x - __half2float(hx));
    __half ly = __float2half_rn(y - __half2float(hy));
    __half2 H = __halves2half2(hx, hy), L = __halves2half2(lx, ly);
    hi = *(uint32_t*)&H; lo = *(uint32_t*)&L;
}
__device__ __forceinline__ void fsplit(float x, __half& h, __half& l){
    h = __float2half_rn(x);
    l = __float2half_rn(x - __half2float(h));
}
__device__ __forceinline__ uint32_t pack_h2(float x, float y){
    __half2 p = __floats2half2_rn(x, y);
    return *(uint32_t*)&p;
}
__device__ __forceinline__ void load_tile(uint32_t sdst, const __half* g,
                                          int rows, int gstride){
    for (int i = threadIdx.x; i < rows * 8; i += THR){
        int r = i >> 3, c = i & 7;
        uint32_t off = (uint32_t)r * 128u + (uint32_t)c * 16u;
        uint32_t sw  = off ^ ((off >> 3) & 0x70);
        CPA(sdst + sw, (const char*)(g + (size_t)r * gstride) + c * 16);
    }
}

// One 64-deep K-tile of split-fp16 NT GEMM for one warp, 16x64 tile.
// full=true: 3-term (hi*hi + hi*lo + lo*hi). full=false: drop lo*hi.
__device__ __forceinline__ void compute_ktile1(
    float (*c)[4], uint32_t sAh, uint32_t sAl, uint32_t sBh, uint32_t sBl,
    int m0, int n0, int lane, bool full)
{
#pragma unroll
    for (int kk = 0; kk < 4; kk++){
        uint32_t aH[4], aL[4];
        {
            int rr = m0 + (lane & 15);
            int cb = kk * 32 + (lane >> 4) * 16;
            ldsm4(aH, swa(sAh, rr, cb));
            ldsm4(aL, swa(sAl, rr, cb));
        }
#pragma unroll
        for (int nq = 0; nq < 4; nq++){
            uint32_t bH[4], bL[4];
            int rr = n0 + nq * 16 + (lane & 15);
            int cb = kk * 32 + (lane >> 4) * 16;
            ldsm4(bH, swa(sBh, rr, cb));
            ldsm4(bL, swa(sBl, rr, cb));
            mma16816(c[2*nq],   aH, bH[0], bH[2]);
            mma16816(c[2*nq],   aH, bL[0], bL[2]);
            mma16816(c[2*nq+1], aH, bH[1], bH[3]);
            mma16816(c[2*nq+1], aH, bL[1], bL[3]);
            if (full){
                mma16816(c[2*nq],   aL, bH[0], bH[2]);
                mma16816(c[2*nq+1], aL, bH[1], bH[3]);
            }
        }
    }
}

// ---------------- prep ------------------------------------------------------
__global__ void __launch_bounds__(256) k_splitX(const float4* __restrict__ X){
    int i = blockIdx.x * 256 + threadIdx.x;
    float4 v = X[i];
    uint32_t h0, l0, h1, l1;
    split2(v.x, v.y, h0, l0);
    split2(v.z, v.w, h1, l1);
    ((uint2*)g_Xh)[i] = make_uint2(h0, h1);
    ((uint2*)g_Xl)[i] = make_uint2(l0, l1);
}

__global__ void __launch_bounds__(256) k_splitW(const float* __restrict__ Wq,
                                                const float* __restrict__ Wk,
                                                const float* __restrict__ Wv){
    const int z = blockIdx.z;
    const float* __restrict__ W = (z == 0) ? Wq : (z == 1) ? Wk : Wv;
    __shared__ float t[32][33];
    int tx = threadIdx.x, ty = threadIdx.y;      // (32,8)
    int bx = blockIdx.x * 32, by = blockIdx.y * 32;
#pragma unroll
    for (int i = 0; i < 32; i += 8)
        t[ty + i][tx] = W[(size_t)(by + ty + i) * DIM + bx + tx];
    __syncthreads();
#pragma unroll
    for (int i = 0; i < 32; i += 8){
        int n = bx + ty + i, k = by + tx;
        __half h, l; fsplit(t[tx][ty + i], h, l);
        size_t o = (size_t)z * DIM * DIM + (size_t)n * DIM + k;
        g_Wth[o] = h; g_Wtl[o] = l;
    }
}

// ---------------- QKV: X[4096,1024] @ Wt[N,K]^T, 16 warps -------------------
#define QKV_STAGE 65536
#define QKV_SMEM  (2 * QKV_STAGE)
__global__ void __launch_bounds__(THR) k_qkv_mma(){
    extern __shared__ __align__(1024) char smraw[];
    uint32_t sbase = s2u(smraw);
    const int tid = threadIdx.x, w = tid >> 5, lane = tid & 31;
    const int z  = blockIdx.z;
    const int bm = blockIdx.y * 128;
    const int bn = blockIdx.x * 128;

    const __half* Ah = g_Xh + (size_t)bm * DIM;
    const __half* Al = g_Xl + (size_t)bm * DIM;
    const __half* Bh = g_Wth + (size_t)z * DIM * DIM + (size_t)bn * DIM;
    const __half* Bl = g_Wtl + (size_t)z * DIM * DIM + (size_t)bn * DIM;

    float c[8][4];
#pragma unroll
    for (int b = 0; b < 8; b++)
#pragma unroll
        for (int d = 0; d < 4; d++) c[b][d] = 0.f;

    const int m0 = (w & 7) * 16, n0 = (w >> 3) * 64;
    const int NT = DIM / 64;   // 16
    const bool full = (z < 2);   // V tolerates 2-term split

    {
        uint32_t buf = sbase;
        load_tile(buf,         Ah, 128, DIM);
        load_tile(buf + 16384, Al, 128, DIM);
        load_tile(buf + 32768, Bh, 128, DIM);
        load_tile(buf + 49152, Bl, 128, DIM);
        CPA_COMMIT();
    }
    for (int kt = 0; kt < NT; kt++){
        if (kt + 1 < NT){
            uint32_t buf = sbase + ((kt + 1) & 1) * QKV_STAGE;
            load_tile(buf,         Ah + (kt+1) * 64, 128, DIM);
            load_tile(buf + 16384, Al + (kt+1) * 64, 128, DIM);
            load_tile(buf + 32768, Bh + (kt+1) * 64, 128, DIM);
            load_tile(buf + 49152, Bl + (kt+1) * 64, 128, DIM);
            CPA_COMMIT();
            CPA_WAIT(1);
        } else {
            CPA_WAIT(0);
        }
        __syncthreads();
        uint32_t buf = sbase + (kt & 1) * QKV_STAGE;
        compute_ktile1(c, buf, buf + 16384, buf + 32768, buf + 49152,
                       m0, n0, lane, full);
        __syncthreads();
    }

    // Q gets 0.125 * log2(e) so flash can use exp2 directly.
    const float sc = (z == 0) ? 0.125f * 1.4426950408889634f : 1.0f;
    __half* Gh = (z == 0) ? g_Qh : (z == 1) ? g_Kh : g_Vh;
    __half* Gl = (z == 0) ? g_Ql : (z == 1) ? g_Kl : g_Vl;
#pragma unroll
    for (int nt = 0; nt < 8; nt++){
        int n = bn + n0 + nt * 8 + (lane & 3) * 2;
        int h = n >> 6, d = n & 63;
#pragma unroll
        for (int half = 0; half < 2; half++){
            int m = bm + m0 + (lane >> 2) + half * 8;
            int bb = m >> 11, s = m & (SEQ - 1);
            size_t o = ((size_t)(h * NB + bb) * SEQ + s) * DH + d;
            uint32_t hi, lo;
            split2(c[nt][half*2] * sc, c[nt][half*2+1] * sc, hi, lo);
            *(uint32_t*)(Gh + o) = hi;
            *(uint32_t*)(Gl + o) = lo;
        }
    }
}

// ---------------- fused flash attention, 16 warps key-split -----------------
// Per CTA: 128 q rows; warp (wq,wg): q rows [wq*16,+16), keys [wg*64,+64) of
// each staged 128-key tile. Private (m,l,O) per warp; split-K merge at end.
// PV uses fp16 P (no split) x split V: 4 MMAs per (kc,nq) instead of 6.
#define FA_STAGE 65536
#define FA_SMEM  (32768 + 2 * FA_STAGE)
__global__ void __launch_bounds__(THR) k_flash(float* __restrict__ out){
    extern __shared__ __align__(1024) char smraw[];
    uint32_t sbase = s2u(smraw);
    const int tid = threadIdx.x, w = tid >> 5, lane = tid & 31;
    const int wq = w & 7, wg = w >> 3;
    const int z  = blockIdx.y;
    const int bm = blockIdx.x * 128;

    const uint32_t sQh = sbase, sQl = sbase + 16384;
    const uint32_t stg = sbase + 32768;

    const __half* Kh = g_Kh + (size_t)z * SEQ * DH;
    const __half* Kl = g_Kl + (size_t)z * SEQ * DH;
    const __half* Vh = g_Vh + (size_t)z * SEQ * DH;
    const __half* Vl = g_Vl + (size_t)z * SEQ * DH;

    // prologue: Q + stage 0
    load_tile(sQh, g_Qh + ((size_t)z * SEQ + bm) * DH, 128, DH);
    load_tile(sQl, g_Ql + ((size_t)z * SEQ + bm) * DH, 128, DH);
    load_tile(stg,         Kh, 128, DH);
    load_tile(stg + 16384, Kl, 128, DH);
    load_tile(stg + 32768, Vh, 128, DH);
    load_tile(stg + 49152, Vl, 128, DH);
    CPA_COMMIT();

    float co[8][4];
#pragma unroll
    for (int i = 0; i < 8; i++)
#pragma unroll
        for (int j = 0; j < 4; j++) co[i][j] = 0.f;
    float m0 = -1e30f, m1 = -1e30f, l0 = 0.f, l1 = 0.f;

    const int NT = SEQ / 128;   // 16
    for (int kt = 0; kt < NT; kt++){
        if (kt + 1 < NT){
            uint32_t buf = stg + ((kt + 1) & 1) * FA_STAGE;
            load_tile(buf,         Kh + (size_t)(kt+1) * 128 * DH, 128, DH);
            load_tile(buf + 16384, Kl + (size_t)(kt+1) * 128 * DH, 128, DH);
            load_tile(buf + 32768, Vh + (size_t)(kt+1) * 128 * DH, 128, DH);
            load_tile(buf + 49152, Vl + (size_t)(kt+1) * 128 * DH, 128, DH);
            CPA_COMMIT();
            CPA_WAIT(1);
        } else {
            CPA_WAIT(0);
        }
        __syncthreads();

        uint32_t buf = stg + (kt & 1) * FA_STAGE;
        const uint32_t sKh = buf, sKl = buf + 16384;
        const uint32_t sVh = buf + 32768, sVl = buf + 49152;

        // ---- S = Q @ K^T  (16 q-rows x 64 keys per warp, 3-term split) ----
        float cs[8][4];
#pragma unroll
        for (int t = 0; t < 8; t++)
#pragma unroll
            for (int j = 0; j < 4; j++) cs[t][j] = 0.f;
#pragma unroll
        for (int kk = 0; kk < 4; kk++){
            uint32_t qH[4], qL[4];
            {
                int rr = wq * 16 + (lane & 15);
                int cb = kk * 32 + (lane >> 4) * 16;
                ldsm4(qH, swa(sQh, rr, cb));
                ldsm4(qL, swa(sQl, rr, cb));
            }
#pragma unroll
            for (int nq = 0; nq < 4; nq++){
                uint32_t bH[4], bL[4];
                int rr = wg * 64 + nq * 16 + (lane & 15);
                int cb = kk * 32 + (lane >> 4) * 16;
                ldsm4(bH, swa(sKh, rr, cb));
                ldsm4(bL, swa(sKl, rr, cb));
                mma16816(cs[2*nq],   qH, bH[0], bH[2]);
                mma16816(cs[2*nq],   qH, bL[0], bL[2]);
                mma16816(cs[2*nq],   qL, bH[0], bH[2]);
                mma16816(cs[2*nq+1], qH, bH[1], bH[3]);
                mma16816(cs[2*nq+1], qH, bL[1], bL[3]);
                mma16816(cs[2*nq+1], qL, bH[1], bH[3]);
            }
        }

        // ---- online softmax in base-2 (rows r0=lane>>2, r1=r0+8) ----
        float mx0 = -1e30f, mx1 = -1e30f;
#pragma unroll
        for (int t = 0; t < 8; t++){
            mx0 = fmaxf(mx0, fmaxf(cs[t][0], cs[t][1]));
            mx1 = fmaxf(mx1, fmaxf(cs[t][2], cs[t][3]));
        }
        mx0 = fmaxf(mx0, __shfl_xor_sync(0xffffffffu, mx0, 1));
        mx0 = fmaxf(mx0, __shfl_xor_sync(0xffffffffu, mx0, 2));
        mx1 = fmaxf(mx1, __shfl_xor_sync(0xffffffffu, mx1, 1));
        mx1 = fmaxf(mx1, __shfl_xor_sync(0xffffffffu, mx1, 2));

        float mn0 = fmaxf(m0, mx0), mn1 = fmaxf(m1, mx1);
        float sc0 = exp2f(m0 - mn0), sc1 = exp2f(m1 - mn1);
        m0 = mn0; m1 = mn1;

        float sum0 = 0.f, sum1 = 0.f;
#pragma unroll
        for (int t = 0; t < 8; t++){
            cs[t][0] = exp2f(cs[t][0] - m0);
            cs[t][1] = exp2f(cs[t][1] - m0);
            cs[t][2] = exp2f(cs[t][2] - m1);
            cs[t][3] = exp2f(cs[t][3] - m1);
            sum0 += cs[t][0] + cs[t][1];
            sum1 += cs[t][2] + cs[t][3];
        }
        sum0 += __shfl_xor_sync(0xffffffffu, sum0, 1);
        sum0 += __shfl_xor_sync(0xffffffffu, sum0, 2);
        sum1 += __shfl_xor_sync(0xffffffffu, sum1, 1);
        sum1 += __shfl_xor_sync(0xffffffffu, sum1, 2);
        l0 = l0 * sc0 + sum0;
        l1 = l1 * sc1 + sum1;
#pragma unroll
        for (int nt = 0; nt < 8; nt++){
            co[nt][0] *= sc0; co[nt][1] *= sc0;
            co[nt][2] *= sc1; co[nt][3] *= sc1;
        }

        // ---- O += P(fp16) @ (V_h + V_l) (keys wg*64..+64) ----
#pragma unroll
        for (int kc = 0; kc < 4; kc++){
            uint32_t aP[4];
            aP[0] = pack_h2(cs[2*kc][0],   cs[2*kc][1]);
            aP[1] = pack_h2(cs[2*kc][2],   cs[2*kc][3]);
            aP[2] = pack_h2(cs[2*kc+1][0], cs[2*kc+1][1]);
            aP[3] = pack_h2(cs[2*kc+1][2], cs[2*kc+1][3]);
#pragma unroll
            for (int nq = 0; nq < 4; nq++){
                uint32_t bH[4], bL[4];
                int rr = wg * 64 + kc * 16 + ((lane >> 4) & 1) * 8 + (lane & 7);
                int cb = (nq * 16 + ((lane >> 3) & 1) * 8) * 2;
                ldsm4t(bH, swa(sVh, rr, cb));
                ldsm4t(bL, swa(sVl, rr, cb));
                mma16816(co[2*nq],   aP, bH[0], bH[2]);
                mma16816(co[2*nq],   aP, bL[0], bL[2]);
                mma16816(co[2*nq+1], aP, bH[1], bH[3]);
                mma16816(co[2*nq+1], aP, bL[1], bL[3]);
            }
        }
        __syncthreads();
    }

    // ---- split-K merge across wg pairs (exchange via smem) ----
    float* ex = (float*)smraw;
    float* p = ex + ((size_t)(wq * 32 + lane)) * 37;
    if (wg == 1){
#pragma unroll
        for (int i = 0; i < 8; i++)
#pragma unroll
            for (int j = 0; j < 4; j++) p[i*4 + j] = co[i][j];
        p[32] = m0; p[33] = m1; p[34] = l0; p[35] = l1;
    }
    __syncthreads();
    if (wg == 0){
        float m0b = p[32], m1b = p[33], l0b = p[34], l1b = p[35];
        float mm0 = fmaxf(m0, m0b), mm1 = fmaxf(m1, m1b);
        float a0 = exp2f(m0 - mm0), b0 = exp2f(m0b - mm0);
        float a1 = exp2f(m1 - mm1), b1 = exp2f(m1b - mm1);
        float inv0 = 1.f / (l0 * a0 + l0b * b0);
        float inv1 = 1.f / (l1 * a1 + l1b * b1);

        const int r0 = bm + wq * 16 + (lane >> 2);
#pragma unroll
        for (int nt = 0; nt < 8; nt++){
            int n = nt * 8 + (lane & 3) * 2;
            float* d0 = out + ((size_t)z * SEQ + r0) * DH + n;
            float* d1 = out + ((size_t)z * SEQ + r0 + 8) * DH + n;
            float o00 = (co[nt][0] * a0 + p[nt*4+0] * b0) * inv0;
            float o01 = (co[nt][1] * a0 + p[nt*4+1] * b0) * inv0;
            float o10 = (co[nt][2] * a1 + p[nt*4+2] * b1) * inv1;
            float o11 = (co[nt][3] * a1 + p[nt*4+3] * b1) * inv1;
            *(float2*)d0 = make_float2(o00, o01);
            *(float2*)d1 = make_float2(o10, o11);
        }
    }
}

// ---------------------------------------------------------------------------
extern "C" void kernel_launch(void* const* d_in, const int* in_sizes, int n_in,
                              void* d_out, int out_size)
{
    const float* X  = (const float*)d_in[0];
    const float* Wq = (const float*)d_in[1];
    const float* Wk = (const float*)d_in[2];
    const float* Wv = (const float*)d_in[3];
    float* out = (float*)d_out;

    cudaFuncSetAttribute(k_qkv_mma, cudaFuncAttributeMaxDynamicSharedMemorySize, QKV_SMEM);
    cudaFuncSetAttribute(k_flash,   cudaFuncAttributeMaxDynamicSharedMemorySize, FA_SMEM);

    k_splitX <<<4096, 256>>>((const float4*)X);
    k_splitW <<<dim3(32, 32, 3), dim3(32, 8)>>>(Wq, Wk, Wv);
    k_qkv_mma<<<dim3(8, 32, 3), THR, QKV_SMEM>>>();
    k_flash  <<<dim3(SEQ / 128, HB), THR, FA_SMEM>>>(out);
}

// round 8
// speedup vs baseline: 3.6995x; 1.1018x over previous
#include <cuda_runtime.h>
#include <cuda_fp16.h>
#include <cstdint>

#define SEQ 2048
#define DIM 1024
#define DH  64
#define HB  32
#define NB  2
#define THR 512

// ---------------- scratch (static __device__, allocation-free) --------------
static __device__ __half g_Xh[4096*1024], g_Xl[4096*1024];
static __device__ __half g_Wth[3*1024*1024], g_Wtl[3*1024*1024];   // [z][n][k]
static __device__ __half g_Qh[HB*SEQ*DH], g_Ql[HB*SEQ*DH];         // [hb][s][dh]
static __device__ __half g_Kh[HB*SEQ*DH], g_Kl[HB*SEQ*DH];
static __device__ __half g_Vh[HB*SEQ*DH];

// ---------------- helpers ---------------------------------------------------
__device__ __forceinline__ uint32_t s2u(const void* p){
    uint32_t a;
    asm("{ .reg .u64 t; cvta.to.shared.u64 t, %1; cvt.u32.u64 %0, t; }" : "=r"(a) : "l"(p));
    return a;
}
#define CPA(s,g) asm volatile("cp.async.cg.shared.global [%0], [%1], 16;" :: "r"(s), "l"(g))
#define CPA_COMMIT() asm volatile("cp.async.commit_group;" ::: "memory")
#define CPA_WAIT(n)  asm volatile("cp.async.wait_group %0;" :: "n"(n) : "memory")

__device__ __forceinline__ void ldsm4(uint32_t* r, uint32_t a){
    asm volatile("ldmatrix.sync.aligned.m8n8.x4.shared.b16 {%0,%1,%2,%3}, [%4];"
        : "=r"(r[0]), "=r"(r[1]), "=r"(r[2]), "=r"(r[3]) : "r"(a));
}
__device__ __forceinline__ void ldsm4t(uint32_t* r, uint32_t a){
    asm volatile("ldmatrix.sync.aligned.m8n8.x4.trans.shared.b16 {%0,%1,%2,%3}, [%4];"
        : "=r"(r[0]), "=r"(r[1]), "=r"(r[2]), "=r"(r[3]) : "r"(a));
}
__device__ __forceinline__ void mma16816(float* c, const uint32_t* a, uint32_t b0, uint32_t b1){
    asm volatile("mma.sync.aligned.m16n8k16.row.col.f32.f16.f16.f32 "
        "{%0,%1,%2,%3}, {%4,%5,%6,%7}, {%8,%9}, {%0,%1,%2,%3};"
        : "+f"(c[0]), "+f"(c[1]), "+f"(c[2]), "+f"(c[3])
        : "r"(a[0]), "r"(a[1]), "r"(a[2]), "r"(a[3]), "r"(b0), "r"(b1));
}
__device__ __forceinline__ uint32_t swa(uint32_t base, int r, int cb){
    uint32_t off = (uint32_t)r * 128u + (uint32_t)cb;
    return base + (off ^ ((off >> 3) & 0x70));
}
__device__ __forceinline__ void split2(float x, float y, uint32_t& hi, uint32_t& lo){
    __half hx = __float2half_rn(x), hy = __float2half_rn(y);
    __half lx = __float2half_rn(x - __half2float(hx));
    __half ly = __float2half_rn(y - __half2float(hy));
    __half2 H = __halves2half2(hx, hy), L = __halves2half2(lx, ly);
    hi = *(uint32_t*)&H; lo = *(uint32_t*)&L;
}
__device__ __forceinline__ void fsplit(float x, __half& h, __half& l){
    h = __float2half_rn(x);
    l = __float2half_rn(x - __half2float(h));
}
__device__ __forceinline__ uint32_t pack_h2(float x, float y){
    __half2 p = __floats2half2_rn(x, y);
    return *(uint32_t*)&p;
}
__device__ __forceinline__ void load_tile(uint32_t sdst, const __half* g,
                                          int rows, int gstride){
    for (int i = threadIdx.x; i < rows * 8; i += THR){
        int r = i >> 3, c = i & 7;
        uint32_t off = (uint32_t)r * 128u + (uint32_t)c * 16u;
        uint32_t sw  = off ^ ((off >> 3) & 0x70);
        CPA(sdst + sw, (const char*)(g + (size_t)r * gstride) + c * 16);
    }
}

// One 64-deep K-tile of split-fp16 NT GEMM for one warp, 16x64 tile.
// full=true: 3-term (hi*hi + hi*lo + lo*hi). full=false: drop lo*hi.
__device__ __forceinline__ void compute_ktile1(
    float (*c)[4], uint32_t sAh, uint32_t sAl, uint32_t sBh, uint32_t sBl,
    int m0, int n0, int lane, bool full)
{
#pragma unroll
    for (int kk = 0; kk < 4; kk++){
        uint32_t aH[4], aL[4];
        {
            int rr = m0 + (lane & 15);
            int cb = kk * 32 + (lane >> 4) * 16;
            ldsm4(aH, swa(sAh, rr, cb));
            ldsm4(aL, swa(sAl, rr, cb));
        }
#pragma unroll
        for (int nq = 0; nq < 4; nq++){
            uint32_t bH[4], bL[4];
            int rr = n0 + nq * 16 + (lane & 15);
            int cb = kk * 32 + (lane >> 4) * 16;
            ldsm4(bH, swa(sBh, rr, cb));
            ldsm4(bL, swa(sBl, rr, cb));
            mma16816(c[2*nq],   aH, bH[0], bH[2]);
            mma16816(c[2*nq],   aH, bL[0], bL[2]);
            mma16816(c[2*nq+1], aH, bH[1], bH[3]);
            mma16816(c[2*nq+1], aH, bL[1], bL[3]);
            if (full){
                mma16816(c[2*nq],   aL, bH[0], bH[2]);
                mma16816(c[2*nq+1], aL, bH[1], bH[3]);
            }
        }
    }
}

// ---------------- prep ------------------------------------------------------
__global__ void __launch_bounds__(256) k_splitX(const float4* __restrict__ X){
    int i = blockIdx.x * 256 + threadIdx.x;
    float4 v = X[i];
    uint32_t h0, l0, h1, l1;
    split2(v.x, v.y, h0, l0);
    split2(v.z, v.w, h1, l1);
    ((uint2*)g_Xh)[i] = make_uint2(h0, h1);
    ((uint2*)g_Xl)[i] = make_uint2(l0, l1);
}

__global__ void __launch_bounds__(256) k_splitW(const float* __restrict__ Wq,
                                                const float* __restrict__ Wk,
                                                const float* __restrict__ Wv){
    const int z = blockIdx.z;
    const float* __restrict__ W = (z == 0) ? Wq : (z == 1) ? Wk : Wv;
    __shared__ float t[32][33];
    int tx = threadIdx.x, ty = threadIdx.y;      // (32,8)
    int bx = blockIdx.x * 32, by = blockIdx.y * 32;
#pragma unroll
    for (int i = 0; i < 32; i += 8)
        t[ty + i][tx] = W[(size_t)(by + ty + i) * DIM + bx + tx];
    __syncthreads();
#pragma unroll
    for (int i = 0; i < 32; i += 8){
        int n = bx + ty + i, k = by + tx;
        __half h, l; fsplit(t[tx][ty + i], h, l);
        size_t o = (size_t)z * DIM * DIM + (size_t)n * DIM + k;
        g_Wth[o] = h; g_Wtl[o] = l;
    }
}

// ---------------- QKV: X[4096,1024] @ Wt[N,K]^T, 16 warps -------------------
#define QKV_STAGE 65536
#define QKV_SMEM  (2 * QKV_STAGE)
__global__ void __launch_bounds__(THR) k_qkv_mma(){
    extern __shared__ __align__(1024) char smraw[];
    uint32_t sbase = s2u(smraw);
    const int tid = threadIdx.x, w = tid >> 5, lane = tid & 31;
    const int z  = blockIdx.z;
    const int bm = blockIdx.y * 128;
    const int bn = blockIdx.x * 128;

    const __half* Ah = g_Xh + (size_t)bm * DIM;
    const __half* Al = g_Xl + (size_t)bm * DIM;
    const __half* Bh = g_Wth + (size_t)z * DIM * DIM + (size_t)bn * DIM;
    const __half* Bl = g_Wtl + (size_t)z * DIM * DIM + (size_t)bn * DIM;

    float c[8][4];
#pragma unroll
    for (int b = 0; b < 8; b++)
#pragma unroll
        for (int d = 0; d < 4; d++) c[b][d] = 0.f;

    const int m0 = (w & 7) * 16, n0 = (w >> 3) * 64;
    const int NT = DIM / 64;   // 16
    const bool full = (z < 2);   // V tolerates 2-term split

    {
        uint32_t buf = sbase;
        load_tile(buf,         Ah, 128, DIM);
        load_tile(buf + 16384, Al, 128, DIM);
        load_tile(buf + 32768, Bh, 128, DIM);
        load_tile(buf + 49152, Bl, 128, DIM);
        CPA_COMMIT();
    }
    for (int kt = 0; kt < NT; kt++){
        if (kt + 1 < NT){
            uint32_t buf = sbase + ((kt + 1) & 1) * QKV_STAGE;
            load_tile(buf,         Ah + (kt+1) * 64, 128, DIM);
            load_tile(buf + 16384, Al + (kt+1) * 64, 128, DIM);
            load_tile(buf + 32768, Bh + (kt+1) * 64, 128, DIM);
            load_tile(buf + 49152, Bl + (kt+1) * 64, 128, DIM);
            CPA_COMMIT();
            CPA_WAIT(1);
        } else {
            CPA_WAIT(0);
        }
        __syncthreads();
        uint32_t buf = sbase + (kt & 1) * QKV_STAGE;
        compute_ktile1(c, buf, buf + 16384, buf + 32768, buf + 49152,
                       m0, n0, lane, full);
        __syncthreads();
    }

    // Q gets 0.125 * log2(e) so flash can use exp2 directly.
    const float sc = (z == 0) ? 0.125f * 1.4426950408889634f : 1.0f;
#pragma unroll
    for (int nt = 0; nt < 8; nt++){
        int n = bn + n0 + nt * 8 + (lane & 3) * 2;
        int h = n >> 6, d = n & 63;
#pragma unroll
        for (int half = 0; half < 2; half++){
            int m = bm + m0 + (lane >> 2) + half * 8;
            int bb = m >> 11, s = m & (SEQ - 1);
            size_t o = ((size_t)(h * NB + bb) * SEQ + s) * DH + d;
            if (z == 2){
                *(uint32_t*)(g_Vh + o) = pack_h2(c[nt][half*2], c[nt][half*2+1]);
            } else {
                uint32_t hi, lo;
                split2(c[nt][half*2] * sc, c[nt][half*2+1] * sc, hi, lo);
                __half* Gh = (z == 0) ? g_Qh : g_Kh;
                __half* Gl = (z == 0) ? g_Ql : g_Kl;
                *(uint32_t*)(Gh + o) = hi;
                *(uint32_t*)(Gl + o) = lo;
            }
        }
    }
}

// ---------------- fused flash attention, 16 warps key-split -----------------
// Per CTA: 128 q rows; warp (wq,wg): q rows [wq*16,+16), keys [wg*64,+64) of
// each staged 128-key tile. Private (m,l,O) per warp; split-K merge at end.
// PV uses fp16 P x fp16 V (2 MMAs per (kc,nq)). Q fragments hoisted to regs.
#define FA_STAGE 49152
#define FA_SMEM  (32768 + 2 * FA_STAGE)
__global__ void __launch_bounds__(THR) k_flash(float* __restrict__ out){
    extern __shared__ __align__(1024) char smraw[];
    uint32_t sbase = s2u(smraw);
    const int tid = threadIdx.x, w = tid >> 5, lane = tid & 31;
    const int wq = w & 7, wg = w >> 3;
    const int z  = blockIdx.y;
    const int bm = blockIdx.x * 128;

    const uint32_t sQh = sbase, sQl = sbase + 16384;
    const uint32_t stg = sbase + 32768;

    const __half* Kh = g_Kh + (size_t)z * SEQ * DH;
    const __half* Kl = g_Kl + (size_t)z * SEQ * DH;
    const __half* Vh = g_Vh + (size_t)z * SEQ * DH;

    // prologue: Q + stage 0
    load_tile(sQh, g_Qh + ((size_t)z * SEQ + bm) * DH, 128, DH);
    load_tile(sQl, g_Ql + ((size_t)z * SEQ + bm) * DH, 128, DH);
    load_tile(stg,         Kh, 128, DH);
    load_tile(stg + 16384, Kl, 128, DH);
    load_tile(stg + 32768, Vh, 128, DH);
    CPA_COMMIT();

    float co[8][4];
#pragma unroll
    for (int i = 0; i < 8; i++)
#pragma unroll
        for (int j = 0; j < 4; j++) co[i][j] = 0.f;
    float m0 = -1e30f, m1 = -1e30f, l0 = 0.f, l1 = 0.f;

    uint32_t qH[4][4], qL[4][4];

    const int NT = SEQ / 128;   // 16
    for (int kt = 0; kt < NT; kt++){
        if (kt + 1 < NT){
            uint32_t buf = stg + ((kt + 1) & 1) * FA_STAGE;
            load_tile(buf,         Kh + (size_t)(kt+1) * 128 * DH, 128, DH);
            load_tile(buf + 16384, Kl + (size_t)(kt+1) * 128 * DH, 128, DH);
            load_tile(buf + 32768, Vh + (size_t)(kt+1) * 128 * DH, 128, DH);
            CPA_COMMIT();
            CPA_WAIT(1);
        } else {
            CPA_WAIT(0);
        }
        __syncthreads();

        if (kt == 0){
            // hoist Q fragments for all 4 k-chunks (32 registers)
#pragma unroll
            for (int kk = 0; kk < 4; kk++){
                int rr = wq * 16 + (lane & 15);
                int cb = kk * 32 + (lane >> 4) * 16;
                ldsm4(qH[kk], swa(sQh, rr, cb));
                ldsm4(qL[kk], swa(sQl, rr, cb));
            }
        }

        uint32_t buf = stg + (kt & 1) * FA_STAGE;
        const uint32_t sKh = buf, sKl = buf + 16384;
        const uint32_t sVh = buf + 32768;

        // ---- S = Q @ K^T  (16 q-rows x 64 keys per warp, 3-term split) ----
        float cs[8][4];
#pragma unroll
        for (int t = 0; t < 8; t++)
#pragma unroll
            for (int j = 0; j < 4; j++) cs[t][j] = 0.f;
#pragma unroll
        for (int kk = 0; kk < 4; kk++){
#pragma unroll
            for (int nq = 0; nq < 4; nq++){
                uint32_t bH[4], bL[4];
                int rr = wg * 64 + nq * 16 + (lane & 15);
                int cb = kk * 32 + (lane >> 4) * 16;
                ldsm4(bH, swa(sKh, rr, cb));
                ldsm4(bL, swa(sKl, rr, cb));
                mma16816(cs[2*nq],   qH[kk], bH[0], bH[2]);
                mma16816(cs[2*nq],   qH[kk], bL[0], bL[2]);
                mma16816(cs[2*nq],   qL[kk], bH[0], bH[2]);
                mma16816(cs[2*nq+1], qH[kk], bH[1], bH[3]);
                mma16816(cs[2*nq+1], qH[kk], bL[1], bL[3]);
                mma16816(cs[2*nq+1], qL[kk], bH[1], bH[3]);
            }
        }

        // ---- online softmax in base-2 (rows r0=lane>>2, r1=r0+8) ----
        float mx0 = -1e30f, mx1 = -1e30f;
#pragma unroll
        for (int t = 0; t < 8; t++){
            mx0 = fmaxf(mx0, fmaxf(cs[t][0], cs[t][1]));
            mx1 = fmaxf(mx1, fmaxf(cs[t][2], cs[t][3]));
        }
        mx0 = fmaxf(mx0, __shfl_xor_sync(0xffffffffu, mx0, 1));
        mx0 = fmaxf(mx0, __shfl_xor_sync(0xffffffffu, mx0, 2));
        mx1 = fmaxf(mx1, __shfl_xor_sync(0xffffffffu, mx1, 1));
        mx1 = fmaxf(mx1, __shfl_xor_sync(0xffffffffu, mx1, 2));

        float mn0 = fmaxf(m0, mx0), mn1 = fmaxf(m1, mx1);
        float sc0 = exp2f(m0 - mn0), sc1 = exp2f(m1 - mn1);
        m0 = mn0; m1 = mn1;

        float sum0 = 0.f, sum1 = 0.f;
#pragma unroll
        for (int t = 0; t < 8; t++){
            cs[t][0] = exp2f(cs[t][0] - m0);
            cs[t][1] = exp2f(cs[t][1] - m0);
            cs[t][2] = exp2f(cs[t][2] - m1);
            cs[t][3] = exp2f(cs[t][3] - m1);
            sum0 += cs[t][0] + cs[t][1];
            sum1 += cs[t][2] + cs[t][3];
        }
        sum0 += __shfl_xor_sync(0xffffffffu, sum0, 1);
        sum0 += __shfl_xor_sync(0xffffffffu, sum0, 2);
        sum1 += __shfl_xor_sync(0xffffffffu, sum1, 1);
        sum1 += __shfl_xor_sync(0xffffffffu, sum1, 2);
        l0 = l0 * sc0 + sum0;
        l1 = l1 * sc1 + sum1;
#pragma unroll
        for (int nt = 0; nt < 8; nt++){
            co[nt][0] *= sc0; co[nt][1] *= sc0;
            co[nt][2] *= sc1; co[nt][3] *= sc1;
        }

        // ---- O += P(fp16) @ V(fp16) (keys wg*64..+64) ----
#pragma unroll
        for (int kc = 0; kc < 4; kc++){
            uint32_t aP[4];
            aP[0] = pack_h2(cs[2*kc][0],   cs[2*kc][1]);
            aP[1] = pack_h2(cs[2*kc][2],   cs[2*kc][3]);
            aP[2] = pack_h2(cs[2*kc+1][0], cs[2*kc+1][1]);
            aP[3] = pack_h2(cs[2*kc+1][2], cs[2*kc+1][3]);
#pragma unroll
            for (int nq = 0; nq < 4; nq++){
                uint32_t bH[4];
                int rr = wg * 64 + kc * 16 + ((lane >> 4) & 1) * 8 + (lane & 7);
                int cb = (nq * 16 + ((lane >> 3) & 1) * 8) * 2;
                ldsm4t(bH, swa(sVh, rr, cb));
                mma16816(co[2*nq],   aP, bH[0], bH[2]);
                mma16816(co[2*nq+1], aP, bH[1], bH[3]);
            }
        }
        __syncthreads();
    }

    // ---- split-K merge across wg pairs (exchange via smem) ----
    float* ex = (float*)smraw;
    float* p = ex + ((size_t)(wq * 32 + lane)) * 37;
    if (wg == 1){
#pragma unroll
        for (int i = 0; i < 8; i++)
#pragma unroll
            for (int j = 0; j < 4; j++) p[i*4 + j] = co[i][j];
        p[32] = m0; p[33] = m1; p[34] = l0; p[35] = l1;
    }
    __syncthreads();
    if (wg == 0){
        float m0b = p[32], m1b = p[33], l0b = p[34], l1b = p[35];
        float mm0 = fmaxf(m0, m0b), mm1 = fmaxf(m1, m1b);
        float a0 = exp2f(m0 - mm0), b0 = exp2f(m0b - mm0);
        float a1 = exp2f(m1 - mm1), b1 = exp2f(m1b - mm1);
        float inv0 = 1.f / (l0 * a0 + l0b * b0);
        float inv1 = 1.f / (l1 * a1 + l1b * b1);

        const int r0 = bm + wq * 16 + (lane >> 2);
#pragma unroll
        for (int nt = 0; nt < 8; nt++){
            int n = nt * 8 + (lane & 3) * 2;
            float* d0 = out + ((size_t)z * SEQ + r0) * DH + n;
            float* d1 = out + ((size_t)z * SEQ + r0 + 8) * DH + n;
            float o00 = (co[nt][0] * a0 + p[nt*4+0] * b0) * inv0;
            float o01 = (co[nt][1] * a0 + p[nt*4+1] * b0) * inv0;
            float o10 = (co[nt][2] * a1 + p[nt*4+2] * b1) * inv1;
            float o11 = (co[nt][3] * a1 + p[nt*4+3] * b1) * inv1;
            *(float2*)d0 = make_float2(o00, o01);
            *(float2*)d1 = make_float2(o10, o11);
        }
    }
}

// ---------------------------------------------------------------------------
extern "C" void kernel_launch(void* const* d_in, const int* in_sizes, int n_in,
                              void* d_out, int out_size)
{
    const float* X  = (const float*)d_in[0];
    const float* Wq = (const float*)d_in[1];
    const float* Wk = (const float*)d_in[2];
    const float* Wv = (const float*)d_in[3];
    float* out = (float*)d_out;

    cudaFuncSetAttribute(k_qkv_mma, cudaFuncAttributeMaxDynamicSharedMemorySize, QKV_SMEM);
    cudaFuncSetAttribute(k_flash,   cudaFuncAttributeMaxDynamicSharedMemorySize, FA_SMEM);

    k_splitX <<<4096, 256>>>((const float4*)X);
    k_splitW <<<dim3(32, 32, 3), dim3(32, 8)>>>(Wq, Wk, Wv);
    k_qkv_mma<<<dim3(8, 32, 3), THR, QKV_SMEM>>>();
    k_flash  <<<dim3(SEQ / 128, HB), THR, FA_SMEM>>>(out);
}